// round 1
// baseline (speedup 1.0000x reference)
#include <cuda_runtime.h>
#include <cstdint>

// Problem constants (fixed-shape benchmark)
#define H      1024
#define BATCH  32
#define NN     20        // N
#define KKK    10        // K (group size)
#define NK     200       // N*K
#define QQ     2048      // Q_total
#define SROWS  (BATCH * NK)   // 6400 support rows
#define QROWS  (BATCH * QQ)   // 65536 query rows

// Scratch (allocation-free: __device__ globals)
__device__ float g_snorm[(size_t)SROWS * H];          // 26 MB
__device__ float g_qnorm[(size_t)QROWS * H];          // 268 MB
__device__ float g_z[(size_t)BATCH * QQ * NK];        // 52 MB

// ---------------------------------------------------------------------------
// LayerNorm: one block (256 threads) per row of 1024 floats. Each thread owns
// one float4. Biased variance, eps = 1e-5.
// ---------------------------------------------------------------------------
__global__ void ln_kernel(const float* __restrict__ x,
                          const float* __restrict__ gamma,
                          const float* __restrict__ beta,
                          int which /*0=support,1=query*/) {
    const int row  = blockIdx.x;
    const int tid  = threadIdx.x;
    const int lane = tid & 31;
    const int warp = tid >> 5;

    const float4* xr = reinterpret_cast<const float4*>(x) + (size_t)row * (H / 4);
    float4 a = xr[tid];

    float s  = a.x + a.y + a.z + a.w;
    float ss = fmaf(a.x, a.x, fmaf(a.y, a.y, fmaf(a.z, a.z, a.w * a.w)));

    #pragma unroll
    for (int o = 16; o; o >>= 1) {
        s  += __shfl_xor_sync(0xffffffffu, s, o);
        ss += __shfl_xor_sync(0xffffffffu, ss, o);
    }

    __shared__ float rs[8], rss[8];
    if (lane == 0) { rs[warp] = s; rss[warp] = ss; }
    __syncthreads();

    __shared__ float smean, srstd;
    if (warp == 0) {
        float s2  = (lane < 8) ? rs[lane]  : 0.0f;
        float ss2 = (lane < 8) ? rss[lane] : 0.0f;
        #pragma unroll
        for (int o = 4; o; o >>= 1) {
            s2  += __shfl_xor_sync(0xffffffffu, s2, o);
            ss2 += __shfl_xor_sync(0xffffffffu, ss2, o);
        }
        if (lane == 0) {
            float mean = s2 * (1.0f / H);
            float var  = ss2 * (1.0f / H) - mean * mean;
            smean = mean;
            srstd = rsqrtf(var + 1e-5f);
        }
    }
    __syncthreads();

    const float mean = smean, rstd = srstd;
    float4 g  = reinterpret_cast<const float4*>(gamma)[tid];
    float4 bb = reinterpret_cast<const float4*>(beta)[tid];
    float4 o4;
    o4.x = (a.x - mean) * rstd * g.x + bb.x;
    o4.y = (a.y - mean) * rstd * g.y + bb.y;
    o4.z = (a.z - mean) * rstd * g.z + bb.z;
    o4.w = (a.w - mean) * rstd * g.w + bb.w;

    float* outp = which ? g_qnorm : g_snorm;
    reinterpret_cast<float4*>(outp)[(size_t)row * (H / 4) + tid] = o4;
}

// ---------------------------------------------------------------------------
// Batched GEMM (NT): z[b][m][n] = sum_h qnorm[b*QQ+m][h] * snorm[b*NK+n][h]
// Tiles: BM=64, BN=64, BK=16. 256 threads, each computes a 4x4 micro-tile.
// ---------------------------------------------------------------------------
#define BM 64
#define BN 64
#define BK 16

__global__ void gemm_kernel() {
    const int b  = blockIdx.z;
    const int tm = blockIdx.y;   // m tile (32)
    const int tn = blockIdx.x;   // n tile (4, last partial)

    const float* A = g_qnorm + ((size_t)b * QQ + (size_t)tm * BM) * H;
    const float* Bp = g_snorm + (size_t)b * NK * H;
    const int n0 = tn * BN;

    __shared__ float As[BK][BM];
    __shared__ float Bs[BK][BN];

    const int tid  = threadIdx.x;
    const int tx   = tid & 15;          // 16 columns of threads
    const int ty   = tid >> 4;          // 16 rows of threads
    const int lrow = tid >> 2;          // 0..63 (tile row for loads)
    const int lk   = (tid & 3) * 4;     // 0,4,8,12 (k offset for float4 load)

    const int gn = n0 + lrow;           // global support row for B loads
    const bool bvalid = (gn < NK);

    float acc[4][4];
    #pragma unroll
    for (int i = 0; i < 4; i++)
        #pragma unroll
        for (int j = 0; j < 4; j++) acc[i][j] = 0.0f;

    for (int kt = 0; kt < H; kt += BK) {
        // Global loads (float4 along h)
        float4 av = *reinterpret_cast<const float4*>(A + (size_t)lrow * H + kt + lk);
        float4 bv = make_float4(0.f, 0.f, 0.f, 0.f);
        if (bvalid)
            bv = *reinterpret_cast<const float4*>(Bp + (size_t)gn * H + kt + lk);

        __syncthreads();
        As[lk + 0][lrow] = av.x;
        As[lk + 1][lrow] = av.y;
        As[lk + 2][lrow] = av.z;
        As[lk + 3][lrow] = av.w;
        Bs[lk + 0][lrow] = bv.x;
        Bs[lk + 1][lrow] = bv.y;
        Bs[lk + 2][lrow] = bv.z;
        Bs[lk + 3][lrow] = bv.w;
        __syncthreads();

        #pragma unroll
        for (int k = 0; k < BK; k++) {
            float4 am = *reinterpret_cast<const float4*>(&As[k][ty * 4]);
            float4 bn = *reinterpret_cast<const float4*>(&Bs[k][tx * 4]);
            float amv[4] = {am.x, am.y, am.z, am.w};
            float bnv[4] = {bn.x, bn.y, bn.z, bn.w};
            #pragma unroll
            for (int i = 0; i < 4; i++)
                #pragma unroll
                for (int j = 0; j < 4; j++)
                    acc[i][j] = fmaf(amv[i], bnv[j], acc[i][j]);
        }
    }

    // Store to z scratch
    const int mbase = tm * BM + ty * 4;
    const int nbase = n0 + tx * 4;
    #pragma unroll
    for (int i = 0; i < 4; i++) {
        float* zr = g_z + ((size_t)b * QQ + mbase + i) * NK;
        #pragma unroll
        for (int j = 0; j < 4; j++) {
            int n = nbase + j;
            if (n < NK) zr[n] = acc[i][j];
        }
    }
}

// ---------------------------------------------------------------------------
// Epilogue: per (b,q) row of 200 values -> 20 group-maxes, min over 20,
// logits[21], argmax (first-index tie-break). One warp per row.
// ---------------------------------------------------------------------------
__global__ void reduce_kernel(float* __restrict__ out_logits,
                              float* __restrict__ out_pred,
                              int write_pred) {
    const int warp = threadIdx.x >> 5;
    const int lane = threadIdx.x & 31;
    const int row  = blockIdx.x * 8 + warp;   // bq index, 0..65535

    __shared__ float sm[8][NK];
    const float* zr = g_z + (size_t)row * NK;
    for (int i = lane; i < NK; i += 32) sm[warp][i] = zr[i];
    __syncwarp();

    const float NEGF = -3.402823466e38f;
    const float POSF =  3.402823466e38f;

    float m = NEGF;
    if (lane < NN) {
        #pragma unroll
        for (int j = 0; j < KKK; j++) m = fmaxf(m, sm[warp][lane * KKK + j]);
        out_logits[(size_t)row * (NN + 1) + lane] = m;
    }

    // min over the 20 group-maxes
    float mv = (lane < NN) ? m : POSF;
    #pragma unroll
    for (int o = 16; o; o >>= 1) mv = fminf(mv, __shfl_xor_sync(0xffffffffu, mv, o));
    if (lane == 0) out_logits[(size_t)row * (NN + 1) + NN] = mv - 1.0f;

    // argmax over 21 values (min-1 can never win; first-index tie-break)
    float v  = (lane < NN) ? m : NEGF;
    int  idx = lane;
    #pragma unroll
    for (int o = 16; o; o >>= 1) {
        float ov = __shfl_xor_sync(0xffffffffu, v, o);
        int   oi = __shfl_xor_sync(0xffffffffu, idx, o);
        if (ov > v || (ov == v && oi < idx)) { v = ov; idx = oi; }
    }
    if (lane == 0 && write_pred) out_pred[row] = (float)idx;
}

// ---------------------------------------------------------------------------
extern "C" void kernel_launch(void* const* d_in, const int* in_sizes, int n_in,
                              void* d_out, int out_size) {
    const float* support = (const float*)d_in[0];
    const float* query   = (const float*)d_in[1];
    const float* gamma   = (const float*)d_in[2];
    const float* beta    = (const float*)d_in[3];
    float* out = (float*)d_out;

    ln_kernel<<<SROWS, 256>>>(support, gamma, beta, 0);
    ln_kernel<<<QROWS, 256>>>(query,   gamma, beta, 1);

    dim3 grid((NK + BN - 1) / BN, QQ / BM, BATCH);   // (4, 32, 32)
    gemm_kernel<<<grid, 256>>>();

    const int logits_elems = BATCH * QQ * (NN + 1);  // 1,376,256
    const int write_pred   = (out_size >= logits_elems + QROWS) ? 1 : 0;
    reduce_kernel<<<QROWS / 8, 256>>>(out, out + logits_elems, write_pred);
}

// round 3
// speedup vs baseline: 2.4453x; 2.4453x over previous
#include <cuda_runtime.h>
#include <cuda_bf16.h>
#include <cstdint>

// Problem constants (fixed-shape benchmark)
#define H      1024
#define BATCH  32
#define NN     20        // N
#define KKK    10        // K (group size)
#define NK     200       // N*K
#define QQ     2048      // Q_total
#define SROWS  (BATCH * NK)   // 6400 support rows
#define QROWS  (BATCH * QQ)   // 65536 query rows

// Scratch (allocation-free: __device__ globals)
__device__ __nv_bfloat16 g_sh[(size_t)SROWS * H];   // support LN hi
__device__ __nv_bfloat16 g_sl[(size_t)SROWS * H];   // support LN lo
__device__ __nv_bfloat16 g_qh[(size_t)QROWS * H];   // query LN hi
__device__ __nv_bfloat16 g_ql[(size_t)QROWS * H];   // query LN lo
__device__ float g_z[(size_t)BATCH * QQ * NK];      // 52 MB

// ---------------------------------------------------------------------------
// LayerNorm: one block (256 threads) per row of 1024 floats. Each thread owns
// one float4. Emits split-bf16 (hi + residual lo) for tensor-core GEMM.
// ---------------------------------------------------------------------------
__global__ void ln_kernel(const float* __restrict__ x,
                          const float* __restrict__ gamma,
                          const float* __restrict__ beta,
                          int which /*0=support,1=query*/) {
    const int row  = blockIdx.x;
    const int tid  = threadIdx.x;
    const int lane = tid & 31;
    const int warp = tid >> 5;

    const float4* xr = reinterpret_cast<const float4*>(x) + (size_t)row * (H / 4);
    float4 a = xr[tid];

    float s  = a.x + a.y + a.z + a.w;
    float ss = fmaf(a.x, a.x, fmaf(a.y, a.y, fmaf(a.z, a.z, a.w * a.w)));

    #pragma unroll
    for (int o = 16; o; o >>= 1) {
        s  += __shfl_xor_sync(0xffffffffu, s, o);
        ss += __shfl_xor_sync(0xffffffffu, ss, o);
    }

    __shared__ float rs[8], rss[8];
    if (lane == 0) { rs[warp] = s; rss[warp] = ss; }
    __syncthreads();

    __shared__ float smean, srstd;
    if (warp == 0) {
        float s2  = (lane < 8) ? rs[lane]  : 0.0f;
        float ss2 = (lane < 8) ? rss[lane] : 0.0f;
        #pragma unroll
        for (int o = 4; o; o >>= 1) {
            s2  += __shfl_xor_sync(0xffffffffu, s2, o);
            ss2 += __shfl_xor_sync(0xffffffffu, ss2, o);
        }
        if (lane == 0) {
            float mean = s2 * (1.0f / H);
            float var  = ss2 * (1.0f / H) - mean * mean;
            smean = mean;
            srstd = rsqrtf(var + 1e-5f);
        }
    }
    __syncthreads();

    const float mean = smean, rstd = srstd;
    float4 g  = reinterpret_cast<const float4*>(gamma)[tid];
    float4 bb = reinterpret_cast<const float4*>(beta)[tid];
    float o0 = (a.x - mean) * rstd * g.x + bb.x;
    float o1 = (a.y - mean) * rstd * g.y + bb.y;
    float o2 = (a.z - mean) * rstd * g.z + bb.z;
    float o3 = (a.w - mean) * rstd * g.w + bb.w;

    __nv_bfloat16 h0 = __float2bfloat16_rn(o0);
    __nv_bfloat16 h1 = __float2bfloat16_rn(o1);
    __nv_bfloat16 h2 = __float2bfloat16_rn(o2);
    __nv_bfloat16 h3 = __float2bfloat16_rn(o3);
    __nv_bfloat16 l0 = __float2bfloat16_rn(o0 - __bfloat162float(h0));
    __nv_bfloat16 l1 = __float2bfloat16_rn(o1 - __bfloat162float(h1));
    __nv_bfloat16 l2 = __float2bfloat16_rn(o2 - __bfloat162float(h2));
    __nv_bfloat16 l3 = __float2bfloat16_rn(o3 - __bfloat162float(h3));

    __nv_bfloat16* ph = which ? g_qh : g_sh;
    __nv_bfloat16* pl = which ? g_ql : g_sl;
    __nv_bfloat162 hv0, hv1, lv0, lv1;
    hv0.x = h0; hv0.y = h1; hv1.x = h2; hv1.y = h3;
    lv0.x = l0; lv0.y = l1; lv1.x = l2; lv1.y = l3;
    __nv_bfloat162* dsth = reinterpret_cast<__nv_bfloat162*>(ph + (size_t)row * H) + tid * 2;
    __nv_bfloat162* dstl = reinterpret_cast<__nv_bfloat162*>(pl + (size_t)row * H) + tid * 2;
    dsth[0] = hv0; dsth[1] = hv1;
    dstl[0] = lv0; dstl[1] = lv1;
}

// ---------------------------------------------------------------------------
// Tensor-core batched GEMM (NT), split-bf16 x3 for fp32-level accuracy.
// z[b][m][n] = sum_h q[m][h]*s[n][h], computed as Ah*Bh + Ah*Bl + Al*Bh.
// CTA tile: BM=128 x BN=208 (full N, predicated past 200), BK=32.
// 8 warps, warp tile 32x104, mma.sync m16n8k16 bf16 -> f32.
// ---------------------------------------------------------------------------
#define BM  128
#define BN  208
#define BKG 32
#define BKP 34   // padded smem k-stride (bf16 units) to break bank conflicts

__device__ __forceinline__ void mma_bf16(float c[4],
                                         const unsigned a[4],
                                         const unsigned b[2]) {
    asm volatile(
        "mma.sync.aligned.m16n8k16.row.col.f32.bf16.bf16.f32 "
        "{%0,%1,%2,%3}, {%4,%5,%6,%7}, {%8,%9}, {%0,%1,%2,%3};\n"
        : "+f"(c[0]), "+f"(c[1]), "+f"(c[2]), "+f"(c[3])
        : "r"(a[0]), "r"(a[1]), "r"(a[2]), "r"(a[3]), "r"(b[0]), "r"(b[1]));
}

__global__ __launch_bounds__(256, 1) void gemm_kernel() {
    __shared__ __nv_bfloat16 Ah[BM * BKP], Al[BM * BKP];
    __shared__ __nv_bfloat16 Bh[BN * BKP], Bl[BN * BKP];

    const int b   = blockIdx.z;
    const int tm  = blockIdx.y;
    const int tid = threadIdx.x;
    const int warp = tid >> 5, lane = tid & 31;
    const int wm = warp >> 1, wn = warp & 1;
    const int qr = lane >> 2;          // 0..7
    const int qp = (lane & 3) * 2;     // 0,2,4,6

    const __nv_bfloat16* gAh = g_qh + ((size_t)b * QQ + (size_t)tm * BM) * H;
    const __nv_bfloat16* gAl = g_ql + ((size_t)b * QQ + (size_t)tm * BM) * H;
    const __nv_bfloat16* gBh = g_sh + (size_t)b * NK * H;
    const __nv_bfloat16* gBl = g_sl + (size_t)b * NK * H;

    float acc[2][13][4];
    #pragma unroll
    for (int mf = 0; mf < 2; mf++)
        #pragma unroll
        for (int nf = 0; nf < 13; nf++)
            #pragma unroll
            for (int i = 0; i < 4; i++) acc[mf][nf][i] = 0.0f;

    // ---- global fetch into registers ----
    // A: 128x32 bf16 = 512 uint4 per array; thread does idx = tid, tid+256
    // B: 208x32 bf16 = 832 uint4 per array; needs 4 iterations of 256 threads
    //    (idx = tid, +256, +512, +768; guard idx < 832; zero-fill rows >= NK)
    uint4 pah[2], pal[2], pbh[4], pbl[4];

    auto fetch = [&](int kt) {
        #pragma unroll
        for (int it = 0; it < 2; it++) {
            int idx = tid + it * 256;
            int r = idx >> 2, k0 = (idx & 3) * 8;
            pah[it] = *reinterpret_cast<const uint4*>(gAh + (size_t)r * H + kt + k0);
            pal[it] = *reinterpret_cast<const uint4*>(gAl + (size_t)r * H + kt + k0);
        }
        #pragma unroll
        for (int it = 0; it < 4; it++) {
            int idx = tid + it * 256;
            int r = idx >> 2, k0 = (idx & 3) * 8;
            uint4 vh = make_uint4(0, 0, 0, 0), vl = make_uint4(0, 0, 0, 0);
            if (r < NK) {
                vh = *reinterpret_cast<const uint4*>(gBh + (size_t)r * H + kt + k0);
                vl = *reinterpret_cast<const uint4*>(gBl + (size_t)r * H + kt + k0);
            }
            pbh[it] = vh; pbl[it] = vl;
        }
    };

    auto store_smem = [&]() {
        #pragma unroll
        for (int it = 0; it < 2; it++) {
            int idx = tid + it * 256;
            int r = idx >> 2, k0 = (idx & 3) * 8;
            unsigned* dh = reinterpret_cast<unsigned*>(&Ah[r * BKP + k0]);
            unsigned* dl = reinterpret_cast<unsigned*>(&Al[r * BKP + k0]);
            const unsigned* sh_ = reinterpret_cast<const unsigned*>(&pah[it]);
            const unsigned* sl_ = reinterpret_cast<const unsigned*>(&pal[it]);
            #pragma unroll
            for (int j = 0; j < 4; j++) { dh[j] = sh_[j]; dl[j] = sl_[j]; }
        }
        #pragma unroll
        for (int it = 0; it < 4; it++) {
            int idx = tid + it * 256;
            if (idx < 832) {
                int r = idx >> 2, k0 = (idx & 3) * 8;
                unsigned* dh = reinterpret_cast<unsigned*>(&Bh[r * BKP + k0]);
                unsigned* dl = reinterpret_cast<unsigned*>(&Bl[r * BKP + k0]);
                const unsigned* sh_ = reinterpret_cast<const unsigned*>(&pbh[it]);
                const unsigned* sl_ = reinterpret_cast<const unsigned*>(&pbl[it]);
                #pragma unroll
                for (int j = 0; j < 4; j++) { dh[j] = sh_[j]; dl[j] = sl_[j]; }
            }
        }
    };

    fetch(0);
    store_smem();
    __syncthreads();

    for (int kt = 0; kt < H; kt += BKG) {
        const bool more = (kt + BKG) < H;
        if (more) fetch(kt + BKG);

        #pragma unroll
        for (int ks = 0; ks < BKG; ks += 16) {
            unsigned ah[2][4], al[2][4];
            #pragma unroll
            for (int mf = 0; mf < 2; mf++) {
                int r = wm * 32 + mf * 16 + qr;
                int c = ks + qp;
                ah[mf][0] = *reinterpret_cast<const unsigned*>(&Ah[r * BKP + c]);
                ah[mf][1] = *reinterpret_cast<const unsigned*>(&Ah[(r + 8) * BKP + c]);
                ah[mf][2] = *reinterpret_cast<const unsigned*>(&Ah[r * BKP + c + 8]);
                ah[mf][3] = *reinterpret_cast<const unsigned*>(&Ah[(r + 8) * BKP + c + 8]);
                al[mf][0] = *reinterpret_cast<const unsigned*>(&Al[r * BKP + c]);
                al[mf][1] = *reinterpret_cast<const unsigned*>(&Al[(r + 8) * BKP + c]);
                al[mf][2] = *reinterpret_cast<const unsigned*>(&Al[r * BKP + c + 8]);
                al[mf][3] = *reinterpret_cast<const unsigned*>(&Al[(r + 8) * BKP + c + 8]);
            }
            #pragma unroll
            for (int nf = 0; nf < 13; nf++) {
                int n = wn * 104 + nf * 8 + qr;
                int c = ks + qp;
                unsigned bh[2], bl[2];
                bh[0] = *reinterpret_cast<const unsigned*>(&Bh[n * BKP + c]);
                bh[1] = *reinterpret_cast<const unsigned*>(&Bh[n * BKP + c + 8]);
                bl[0] = *reinterpret_cast<const unsigned*>(&Bl[n * BKP + c]);
                bl[1] = *reinterpret_cast<const unsigned*>(&Bl[n * BKP + c + 8]);
                mma_bf16(acc[0][nf], ah[0], bh);
                mma_bf16(acc[1][nf], ah[1], bh);
                mma_bf16(acc[0][nf], ah[0], bl);
                mma_bf16(acc[1][nf], ah[1], bl);
                mma_bf16(acc[0][nf], al[0], bh);
                mma_bf16(acc[1][nf], al[1], bh);
            }
        }

        __syncthreads();
        if (more) {
            store_smem();
            __syncthreads();
        }
    }

    // ---- store z tile ----
    #pragma unroll
    for (int mf = 0; mf < 2; mf++) {
        #pragma unroll
        for (int nf = 0; nf < 13; nf++) {
            int gm = tm * BM + wm * 32 + mf * 16 + qr;
            int gn = wn * 104 + nf * 8 + qp;
            if (gn < NK) {
                float* zr0 = g_z + ((size_t)b * QQ + gm) * NK;
                float* zr1 = g_z + ((size_t)b * QQ + gm + 8) * NK;
                zr0[gn]     = acc[mf][nf][0];
                zr0[gn + 1] = acc[mf][nf][1];
                zr1[gn]     = acc[mf][nf][2];
                zr1[gn + 1] = acc[mf][nf][3];
            }
        }
    }
}

// ---------------------------------------------------------------------------
// Epilogue: per (b,q) row of 200 values -> 20 group-maxes, min over 20,
// logits[21], argmax (first-index tie-break). One warp per row.
// ---------------------------------------------------------------------------
__global__ void reduce_kernel(float* __restrict__ out_logits,
                              float* __restrict__ out_pred,
                              int write_pred) {
    const int warp = threadIdx.x >> 5;
    const int lane = threadIdx.x & 31;
    const int row  = blockIdx.x * 8 + warp;   // bq index, 0..65535

    __shared__ float sm[8][NK];
    const float* zr = g_z + (size_t)row * NK;
    for (int i = lane; i < NK; i += 32) sm[warp][i] = zr[i];
    __syncwarp();

    const float NEGF = -3.402823466e38f;
    const float POSF =  3.402823466e38f;

    float m = NEGF;
    if (lane < NN) {
        #pragma unroll
        for (int j = 0; j < KKK; j++) m = fmaxf(m, sm[warp][lane * KKK + j]);
        out_logits[(size_t)row * (NN + 1) + lane] = m;
    }

    float mv = (lane < NN) ? m : POSF;
    #pragma unroll
    for (int o = 16; o; o >>= 1) mv = fminf(mv, __shfl_xor_sync(0xffffffffu, mv, o));
    if (lane == 0) out_logits[(size_t)row * (NN + 1) + NN] = mv - 1.0f;

    float v  = (lane < NN) ? m : NEGF;
    int  idx = lane;
    #pragma unroll
    for (int o = 16; o; o >>= 1) {
        float ov = __shfl_xor_sync(0xffffffffu, v, o);
        int   oi = __shfl_xor_sync(0xffffffffu, idx, o);
        if (ov > v || (ov == v && oi < idx)) { v = ov; idx = oi; }
    }
    if (lane == 0 && write_pred) out_pred[row] = (float)idx;
}

// ---------------------------------------------------------------------------
extern "C" void kernel_launch(void* const* d_in, const int* in_sizes, int n_in,
                              void* d_out, int out_size) {
    const float* support = (const float*)d_in[0];
    const float* query   = (const float*)d_in[1];
    const float* gamma   = (const float*)d_in[2];
    const float* beta    = (const float*)d_in[3];
    float* out = (float*)d_out;

    ln_kernel<<<SROWS, 256>>>(support, gamma, beta, 0);
    ln_kernel<<<QROWS, 256>>>(query,   gamma, beta, 1);

    dim3 grid(1, QQ / BM, BATCH);   // (1, 16, 32) = 512 CTAs
    gemm_kernel<<<grid, 256>>>();

    const int logits_elems = BATCH * QQ * (NN + 1);  // 1,376,256
    const int write_pred   = (out_size >= logits_elems + QROWS) ? 1 : 0;
    reduce_kernel<<<QROWS / 8, 256>>>(out, out + logits_elems, write_pred);
}

// round 4
// speedup vs baseline: 2.8839x; 1.1794x over previous
#include <cuda_runtime.h>
#include <cuda_bf16.h>
#include <cstdint>

// Problem constants (fixed-shape benchmark)
#define H      1024
#define BATCH  32
#define NN     20        // N
#define KKK    10        // K (group size)
#define NK     200       // N*K
#define QQ     2048      // Q_total
#define SROWS  (BATCH * NK)   // 6400 support rows
#define QROWS  (BATCH * QQ)   // 65536 query rows

// Scratch (allocation-free: __device__ globals)
__device__ __nv_bfloat16 g_sh[(size_t)SROWS * H];   // support LN hi
__device__ __nv_bfloat16 g_sl[(size_t)SROWS * H];   // support LN lo
__device__ __nv_bfloat16 g_qh[(size_t)QROWS * H];   // query LN hi
__device__ __nv_bfloat16 g_ql[(size_t)QROWS * H];   // query LN lo

// ---------------------------------------------------------------------------
// LayerNorm: one block (256 threads) per row of 1024 floats. Each thread owns
// one float4. Emits split-bf16 (hi + residual lo) for tensor-core GEMM.
// ---------------------------------------------------------------------------
__global__ void ln_kernel(const float* __restrict__ x,
                          const float* __restrict__ gamma,
                          const float* __restrict__ beta,
                          int which /*0=support,1=query*/) {
    const int row  = blockIdx.x;
    const int tid  = threadIdx.x;
    const int lane = tid & 31;
    const int warp = tid >> 5;

    const float4* xr = reinterpret_cast<const float4*>(x) + (size_t)row * (H / 4);
    float4 a = xr[tid];

    float s  = a.x + a.y + a.z + a.w;
    float ss = fmaf(a.x, a.x, fmaf(a.y, a.y, fmaf(a.z, a.z, a.w * a.w)));

    #pragma unroll
    for (int o = 16; o; o >>= 1) {
        s  += __shfl_xor_sync(0xffffffffu, s, o);
        ss += __shfl_xor_sync(0xffffffffu, ss, o);
    }

    __shared__ float rs[8], rss[8];
    if (lane == 0) { rs[warp] = s; rss[warp] = ss; }
    __syncthreads();

    __shared__ float smean, srstd;
    if (warp == 0) {
        float s2  = (lane < 8) ? rs[lane]  : 0.0f;
        float ss2 = (lane < 8) ? rss[lane] : 0.0f;
        #pragma unroll
        for (int o = 4; o; o >>= 1) {
            s2  += __shfl_xor_sync(0xffffffffu, s2, o);
            ss2 += __shfl_xor_sync(0xffffffffu, ss2, o);
        }
        if (lane == 0) {
            float mean = s2 * (1.0f / H);
            float var  = ss2 * (1.0f / H) - mean * mean;
            smean = mean;
            srstd = rsqrtf(var + 1e-5f);
        }
    }
    __syncthreads();

    const float mean = smean, rstd = srstd;
    float4 g  = reinterpret_cast<const float4*>(gamma)[tid];
    float4 bb = reinterpret_cast<const float4*>(beta)[tid];
    float o0 = (a.x - mean) * rstd * g.x + bb.x;
    float o1 = (a.y - mean) * rstd * g.y + bb.y;
    float o2 = (a.z - mean) * rstd * g.z + bb.z;
    float o3 = (a.w - mean) * rstd * g.w + bb.w;

    __nv_bfloat16 h0 = __float2bfloat16_rn(o0);
    __nv_bfloat16 h1 = __float2bfloat16_rn(o1);
    __nv_bfloat16 h2 = __float2bfloat16_rn(o2);
    __nv_bfloat16 h3 = __float2bfloat16_rn(o3);
    __nv_bfloat16 l0 = __float2bfloat16_rn(o0 - __bfloat162float(h0));
    __nv_bfloat16 l1 = __float2bfloat16_rn(o1 - __bfloat162float(h1));
    __nv_bfloat16 l2 = __float2bfloat16_rn(o2 - __bfloat162float(h2));
    __nv_bfloat16 l3 = __float2bfloat16_rn(o3 - __bfloat162float(h3));

    __nv_bfloat16* ph = which ? g_qh : g_sh;
    __nv_bfloat16* pl = which ? g_ql : g_sl;
    __nv_bfloat162 hv0, hv1, lv0, lv1;
    hv0.x = h0; hv0.y = h1; hv1.x = h2; hv1.y = h3;
    lv0.x = l0; lv0.y = l1; lv1.x = l2; lv1.y = l3;
    __nv_bfloat162* dsth = reinterpret_cast<__nv_bfloat162*>(ph + (size_t)row * H) + tid * 2;
    __nv_bfloat162* dstl = reinterpret_cast<__nv_bfloat162*>(pl + (size_t)row * H) + tid * 2;
    dsth[0] = hv0; dsth[1] = hv1;
    dstl[0] = lv0; dstl[1] = lv1;
}

// ---------------------------------------------------------------------------
// Tensor-core batched GEMM (NT), split-bf16 x3, cp.async double-buffered,
// with FUSED group-max / min / argmax epilogue (no z scratch roundtrip).
// z[b][m][n] = sum_h q[m][h]*s[n][h], computed as Ah*Bh + Ah*Bl + Al*Bh.
// CTA tile: BM=128 x BN=208 (full N, predicated past 200), BK=32.
// 8 warps, warp tile 32x104, mma.sync m16n8k16 bf16 -> f32.
// ---------------------------------------------------------------------------
#define BM   128
#define BN   208
#define BKG  32
#define BKP  40   // padded smem k-stride (bf16): 80B rows -> conflict-free LDS,
                  // and every (r*BKP + k0)*2 cp.async chunk stays 16B aligned

#define AB_BYTES    (BM * BKP * 2)          // 10240
#define BB_BYTES    (BN * BKP * 2)          // 16640
#define OFF_AH      0
#define OFF_AL      (AB_BYTES)
#define OFF_BH      (2 * AB_BYTES)
#define OFF_BL      (2 * AB_BYTES + BB_BYTES)
#define STAGE_BYTES (2 * AB_BYTES + 2 * BB_BYTES)   // 53760
#define SMEM_TOTAL  (2 * STAGE_BYTES)                // 107520
#define ZST         210                              // z-tile smem stride (floats)

__device__ __forceinline__ void cp16(uint32_t dst, const void* src, bool full) {
    int sz = full ? 16 : 0;
    asm volatile("cp.async.cg.shared.global [%0], [%1], 16, %2;\n"
                 :: "r"(dst), "l"(src), "r"(sz));
}

__device__ __forceinline__ void mma_bf16(float c[4],
                                         const unsigned a[4],
                                         const unsigned b[2]) {
    asm volatile(
        "mma.sync.aligned.m16n8k16.row.col.f32.bf16.bf16.f32 "
        "{%0,%1,%2,%3}, {%4,%5,%6,%7}, {%8,%9}, {%0,%1,%2,%3};\n"
        : "+f"(c[0]), "+f"(c[1]), "+f"(c[2]), "+f"(c[3])
        : "r"(a[0]), "r"(a[1]), "r"(a[2]), "r"(a[3]), "r"(b[0]), "r"(b[1]));
}

extern __shared__ char dsm[];

__global__ __launch_bounds__(256, 1) void gemm_kernel(float* __restrict__ out_logits,
                                                      float* __restrict__ out_pred,
                                                      int write_pred) {
    const int b   = blockIdx.z;
    const int tm  = blockIdx.y;
    const int tid = threadIdx.x;
    const int warp = tid >> 5, lane = tid & 31;
    const int wm = warp >> 1, wn = warp & 1;
    const int qr = lane >> 2;          // 0..7
    const int qp = (lane & 3) * 2;     // 0,2,4,6

    const __nv_bfloat16* gAh = g_qh + ((size_t)b * QQ + (size_t)tm * BM) * H;
    const __nv_bfloat16* gAl = g_ql + ((size_t)b * QQ + (size_t)tm * BM) * H;
    const __nv_bfloat16* gBh = g_sh + (size_t)b * NK * H;
    const __nv_bfloat16* gBl = g_sl + (size_t)b * NK * H;

    const uint32_t smem_u32 = (uint32_t)__cvta_generic_to_shared(dsm);

    float acc[2][13][4];
    #pragma unroll
    for (int mf = 0; mf < 2; mf++)
        #pragma unroll
        for (int nf = 0; nf < 13; nf++)
            #pragma unroll
            for (int i = 0; i < 4; i++) acc[mf][nf][i] = 0.0f;

    // ---- async copy of one k-stage into buffer buf ----
    auto issue = [&](int kt, int buf) {
        uint32_t base = smem_u32 + buf * STAGE_BYTES;
        #pragma unroll
        for (int it = 0; it < 2; it++) {
            int idx = tid + it * 256;            // 0..511
            int r = idx >> 2, k0 = (idx & 3) * 8;
            uint32_t off = (uint32_t)(r * BKP + k0) * 2;
            cp16(base + OFF_AH + off, gAh + (size_t)r * H + kt + k0, true);
            cp16(base + OFF_AL + off, gAl + (size_t)r * H + kt + k0, true);
        }
        #pragma unroll
        for (int it = 0; it < 4; it++) {
            int idx = tid + it * 256;            // 0..1023, need < 832
            if (idx < 832) {
                int r = idx >> 2, k0 = (idx & 3) * 8;
                uint32_t off = (uint32_t)(r * BKP + k0) * 2;
                bool v = (r < NK);
                int rs = v ? r : 0;
                cp16(base + OFF_BH + off, gBh + (size_t)rs * H + kt + k0, v);
                cp16(base + OFF_BL + off, gBl + (size_t)rs * H + kt + k0, v);
            }
        }
        asm volatile("cp.async.commit_group;\n" ::);
    };

    issue(0, 0);

    const int NIT = H / BKG;   // 32
    for (int i = 0; i < NIT; i++) {
        asm volatile("cp.async.wait_group 0;\n" ::);
        __syncthreads();                              // stage i visible; stage i-1 compute done
        if (i + 1 < NIT) issue((i + 1) * BKG, (i + 1) & 1);

        const char* st = dsm + (i & 1) * STAGE_BYTES;
        const __nv_bfloat16* Ah = (const __nv_bfloat16*)(st + OFF_AH);
        const __nv_bfloat16* Al = (const __nv_bfloat16*)(st + OFF_AL);
        const __nv_bfloat16* Bh = (const __nv_bfloat16*)(st + OFF_BH);
        const __nv_bfloat16* Bl = (const __nv_bfloat16*)(st + OFF_BL);

        #pragma unroll
        for (int ks = 0; ks < BKG; ks += 16) {
            unsigned ah[2][4], al[2][4];
            #pragma unroll
            for (int mf = 0; mf < 2; mf++) {
                int r = wm * 32 + mf * 16 + qr;
                int c = ks + qp;
                ah[mf][0] = *reinterpret_cast<const unsigned*>(&Ah[r * BKP + c]);
                ah[mf][1] = *reinterpret_cast<const unsigned*>(&Ah[(r + 8) * BKP + c]);
                ah[mf][2] = *reinterpret_cast<const unsigned*>(&Ah[r * BKP + c + 8]);
                ah[mf][3] = *reinterpret_cast<const unsigned*>(&Ah[(r + 8) * BKP + c + 8]);
                al[mf][0] = *reinterpret_cast<const unsigned*>(&Al[r * BKP + c]);
                al[mf][1] = *reinterpret_cast<const unsigned*>(&Al[(r + 8) * BKP + c]);
                al[mf][2] = *reinterpret_cast<const unsigned*>(&Al[r * BKP + c + 8]);
                al[mf][3] = *reinterpret_cast<const unsigned*>(&Al[(r + 8) * BKP + c + 8]);
            }
            #pragma unroll
            for (int nf = 0; nf < 13; nf++) {
                int n = wn * 104 + nf * 8 + qr;
                int c = ks + qp;
                unsigned bh[2], bl[2];
                bh[0] = *reinterpret_cast<const unsigned*>(&Bh[n * BKP + c]);
                bh[1] = *reinterpret_cast<const unsigned*>(&Bh[n * BKP + c + 8]);
                bl[0] = *reinterpret_cast<const unsigned*>(&Bl[n * BKP + c]);
                bl[1] = *reinterpret_cast<const unsigned*>(&Bl[n * BKP + c + 8]);
                mma_bf16(acc[0][nf], ah[0], bh);
                mma_bf16(acc[1][nf], ah[1], bh);
                mma_bf16(acc[0][nf], ah[0], bl);
                mma_bf16(acc[1][nf], ah[1], bl);
                mma_bf16(acc[0][nf], al[0], bh);
                mma_bf16(acc[1][nf], al[1], bh);
            }
        }
    }

    // ---- fused epilogue: 4 chunks of 32 rows through smem ----
    __syncthreads();
    float* zs = (float*)dsm;                    // 32 x ZST floats = 26.9 KB
    const float NEGF = -3.402823466e38f;
    const float POSF =  3.402823466e38f;

    #pragma unroll 1
    for (int c = 0; c < 4; c++) {
        if (wm == c) {
            #pragma unroll
            for (int mf = 0; mf < 2; mf++)
                #pragma unroll
                for (int nf = 0; nf < 13; nf++) {
                    int r0  = mf * 16 + qr;
                    int col = wn * 104 + nf * 8 + qp;
                    *reinterpret_cast<float2*>(&zs[r0 * ZST + col]) =
                        make_float2(acc[mf][nf][0], acc[mf][nf][1]);
                    *reinterpret_cast<float2*>(&zs[(r0 + 8) * ZST + col]) =
                        make_float2(acc[mf][nf][2], acc[mf][nf][3]);
                }
        }
        __syncthreads();

        #pragma unroll
        for (int rr = 0; rr < 4; rr++) {
            int rl = warp * 4 + rr;
            int gq = tm * BM + c * 32 + rl;                 // q index in batch
            size_t orow = ((size_t)b * QQ + gq) * (NN + 1);

            float m = NEGF;
            if (lane < NN) {
                #pragma unroll
                for (int j = 0; j < KKK; j++)
                    m = fmaxf(m, zs[rl * ZST + lane * KKK + j]);
                out_logits[orow + lane] = m;
            }

            float mv = (lane < NN) ? m : POSF;
            #pragma unroll
            for (int o = 16; o; o >>= 1)
                mv = fminf(mv, __shfl_xor_sync(0xffffffffu, mv, o));
            if (lane == 0) out_logits[orow + NN] = mv - 1.0f;

            float v  = (lane < NN) ? m : NEGF;
            int  idx = lane;
            #pragma unroll
            for (int o = 16; o; o >>= 1) {
                float ov = __shfl_xor_sync(0xffffffffu, v, o);
                int   oi = __shfl_xor_sync(0xffffffffu, idx, o);
                if (ov > v || (ov == v && oi < idx)) { v = ov; idx = oi; }
            }
            if (lane == 0 && write_pred)
                out_pred[(size_t)b * QQ + gq] = (float)idx;
        }
        __syncthreads();
    }
}

// ---------------------------------------------------------------------------
extern "C" void kernel_launch(void* const* d_in, const int* in_sizes, int n_in,
                              void* d_out, int out_size) {
    const float* support = (const float*)d_in[0];
    const float* query   = (const float*)d_in[1];
    const float* gamma   = (const float*)d_in[2];
    const float* beta    = (const float*)d_in[3];
    float* out = (float*)d_out;

    // Opt-in to >48KB dynamic smem (idempotent; immediate API, not a stream op)
    cudaFuncSetAttribute(gemm_kernel,
                         cudaFuncAttributeMaxDynamicSharedMemorySize, SMEM_TOTAL);

    ln_kernel<<<SROWS, 256>>>(support, gamma, beta, 0);
    ln_kernel<<<QROWS, 256>>>(query,   gamma, beta, 1);

    const int logits_elems = BATCH * QQ * (NN + 1);  // 1,376,256
    const int write_pred   = (out_size >= logits_elems + QROWS) ? 1 : 0;

    dim3 grid(1, QQ / BM, BATCH);   // (1, 16, 32) = 512 CTAs
    gemm_kernel<<<grid, 256, SMEM_TOTAL>>>(out, out + logits_elems, write_pred);
}

// round 5
// speedup vs baseline: 3.0693x; 1.0643x over previous
#include <cuda_runtime.h>
#include <cuda_bf16.h>
#include <cstdint>

// Problem constants (fixed-shape benchmark)
#define H      1024
#define BATCH  32
#define NN     20        // N
#define KKK    10        // K (group size)
#define NK     200       // N*K
#define QQ     2048      // Q_total
#define SROWS  (BATCH * NK)   // 6400 support rows
#define QROWS  (BATCH * QQ)   // 65536 query rows

// Scratch (allocation-free: __device__ globals)
__device__ __nv_bfloat16 g_sh[(size_t)SROWS * H];   // support LN hi
__device__ __nv_bfloat16 g_sl[(size_t)SROWS * H];   // support LN lo
__device__ __nv_bfloat16 g_qh[(size_t)QROWS * H];   // query LN hi
__device__ __nv_bfloat16 g_ql[(size_t)QROWS * H];   // query LN lo

// ---------------------------------------------------------------------------
// LayerNorm, warp-per-row: 8 warps/block = 8 rows/block, zero block syncs.
// Each lane owns 8 float4 (MLP=8). Emits split-bf16 (hi + residual lo).
// ---------------------------------------------------------------------------
__global__ __launch_bounds__(256) void ln_kernel(const float* __restrict__ x,
                          const float* __restrict__ gamma,
                          const float* __restrict__ beta,
                          int which /*0=support,1=query*/) {
    const int lane = threadIdx.x & 31;
    const int warp = threadIdx.x >> 5;
    const int row  = blockIdx.x * 8 + warp;

    const float4* xr = reinterpret_cast<const float4*>(x) + (size_t)row * (H / 4);
    float4 a[8];
    #pragma unroll
    for (int i = 0; i < 8; i++) a[i] = xr[lane + i * 32];

    float s = 0.0f, ss = 0.0f;
    #pragma unroll
    for (int i = 0; i < 8; i++) {
        s  += (a[i].x + a[i].y) + (a[i].z + a[i].w);
        ss += fmaf(a[i].x, a[i].x, fmaf(a[i].y, a[i].y,
               fmaf(a[i].z, a[i].z, a[i].w * a[i].w)));
    }
    #pragma unroll
    for (int o = 16; o; o >>= 1) {
        s  += __shfl_xor_sync(0xffffffffu, s, o);
        ss += __shfl_xor_sync(0xffffffffu, ss, o);
    }
    const float mean = s * (1.0f / H);
    const float var  = ss * (1.0f / H) - mean * mean;
    const float rstd = rsqrtf(var + 1e-5f);

    __nv_bfloat16* ph = which ? g_qh : g_sh;
    __nv_bfloat16* pl = which ? g_ql : g_sl;
    uint2* dsth = reinterpret_cast<uint2*>(ph + (size_t)row * H);
    uint2* dstl = reinterpret_cast<uint2*>(pl + (size_t)row * H);
    const float4* g4 = reinterpret_cast<const float4*>(gamma);
    const float4* b4 = reinterpret_cast<const float4*>(beta);

    #pragma unroll
    for (int i = 0; i < 8; i++) {
        const int idx = lane + i * 32;
        float4 g  = g4[idx];
        float4 bb = b4[idx];
        float o0 = (a[i].x - mean) * rstd * g.x + bb.x;
        float o1 = (a[i].y - mean) * rstd * g.y + bb.y;
        float o2 = (a[i].z - mean) * rstd * g.z + bb.z;
        float o3 = (a[i].w - mean) * rstd * g.w + bb.w;

        __nv_bfloat16 h0 = __float2bfloat16_rn(o0);
        __nv_bfloat16 h1 = __float2bfloat16_rn(o1);
        __nv_bfloat16 h2 = __float2bfloat16_rn(o2);
        __nv_bfloat16 h3 = __float2bfloat16_rn(o3);
        __nv_bfloat162 hv0, hv1;
        hv0.x = h0; hv0.y = h1; hv1.x = h2; hv1.y = h3;
        uint2 hp;
        hp.x = *reinterpret_cast<unsigned*>(&hv0);
        hp.y = *reinterpret_cast<unsigned*>(&hv1);
        dsth[idx] = hp;

        __nv_bfloat162 lv0, lv1;
        lv0.x = __float2bfloat16_rn(o0 - __bfloat162float(h0));
        lv0.y = __float2bfloat16_rn(o1 - __bfloat162float(h1));
        lv1.x = __float2bfloat16_rn(o2 - __bfloat162float(h2));
        lv1.y = __float2bfloat16_rn(o3 - __bfloat162float(h3));
        uint2 lp;
        lp.x = *reinterpret_cast<unsigned*>(&lv0);
        lp.y = *reinterpret_cast<unsigned*>(&lv1);
        dstl[idx] = lp;
    }
}

// ---------------------------------------------------------------------------
// Tensor-core batched GEMM (NT), split-bf16 x3, cp.async 3-stage pipeline,
// with FUSED group-max / min / argmax epilogue (no z scratch roundtrip).
// z[b][m][n] = sum_h q[m][h]*s[n][h], computed as Ah*Bh + Ah*Bl + Al*Bh.
// CTA tile: BM=128 x BN=208 (full N, predicated past 200), BK=32.
// 8 warps, warp tile 32x104, mma.sync m16n8k16 bf16 -> f32.
// ---------------------------------------------------------------------------
#define BM   128
#define BN   208
#define BKG  32
#define BKP  40   // padded smem k-stride (bf16): 80B rows -> conflict-free LDS,
                  // and every (r*BKP + k0)*2 cp.async chunk stays 16B aligned

#define AB_BYTES    (BM * BKP * 2)          // 10240
#define BB_BYTES    (BN * BKP * 2)          // 16640
#define OFF_AH      0
#define OFF_AL      (AB_BYTES)
#define OFF_BH      (2 * AB_BYTES)
#define OFF_BL      (2 * AB_BYTES + BB_BYTES)
#define STAGE_BYTES (2 * AB_BYTES + 2 * BB_BYTES)   // 53760
#define NSTAGE      3
#define SMEM_TOTAL  (NSTAGE * STAGE_BYTES)          // 161280
#define ZST         210                             // z-tile smem stride (floats)

__device__ __forceinline__ void cp16(uint32_t dst, const void* src, bool full) {
    int sz = full ? 16 : 0;
    asm volatile("cp.async.cg.shared.global [%0], [%1], 16, %2;\n"
                 :: "r"(dst), "l"(src), "r"(sz));
}

__device__ __forceinline__ void mma_bf16(float c[4],
                                         const unsigned a[4],
                                         const unsigned b[2]) {
    asm volatile(
        "mma.sync.aligned.m16n8k16.row.col.f32.bf16.bf16.f32 "
        "{%0,%1,%2,%3}, {%4,%5,%6,%7}, {%8,%9}, {%0,%1,%2,%3};\n"
        : "+f"(c[0]), "+f"(c[1]), "+f"(c[2]), "+f"(c[3])
        : "r"(a[0]), "r"(a[1]), "r"(a[2]), "r"(a[3]), "r"(b[0]), "r"(b[1]));
}

extern __shared__ char dsm[];

__global__ __launch_bounds__(256, 1) void gemm_kernel(float* __restrict__ out_logits,
                                                      float* __restrict__ out_pred,
                                                      int write_pred) {
    const int b   = blockIdx.z;
    const int tm  = blockIdx.y;
    const int tid = threadIdx.x;
    const int warp = tid >> 5, lane = tid & 31;
    const int wm = warp >> 1, wn = warp & 1;
    const int qr = lane >> 2;          // 0..7
    const int qp = (lane & 3) * 2;     // 0,2,4,6

    const __nv_bfloat16* gAh = g_qh + ((size_t)b * QQ + (size_t)tm * BM) * H;
    const __nv_bfloat16* gAl = g_ql + ((size_t)b * QQ + (size_t)tm * BM) * H;
    const __nv_bfloat16* gBh = g_sh + (size_t)b * NK * H;
    const __nv_bfloat16* gBl = g_sl + (size_t)b * NK * H;

    const uint32_t smem_u32 = (uint32_t)__cvta_generic_to_shared(dsm);

    float acc[2][13][4];
    #pragma unroll
    for (int mf = 0; mf < 2; mf++)
        #pragma unroll
        for (int nf = 0; nf < 13; nf++)
            #pragma unroll
            for (int i = 0; i < 4; i++) acc[mf][nf][i] = 0.0f;

    // ---- async copy of one k-stage into buffer buf ----
    auto issue = [&](int kt, int buf) {
        uint32_t base = smem_u32 + buf * STAGE_BYTES;
        #pragma unroll
        for (int it = 0; it < 2; it++) {
            int idx = tid + it * 256;            // 0..511
            int r = idx >> 2, k0 = (idx & 3) * 8;
            uint32_t off = (uint32_t)(r * BKP + k0) * 2;
            cp16(base + OFF_AH + off, gAh + (size_t)r * H + kt + k0, true);
            cp16(base + OFF_AL + off, gAl + (size_t)r * H + kt + k0, true);
        }
        #pragma unroll
        for (int it = 0; it < 4; it++) {
            int idx = tid + it * 256;            // 0..1023, need < 832
            if (idx < 832) {
                int r = idx >> 2, k0 = (idx & 3) * 8;
                uint32_t off = (uint32_t)(r * BKP + k0) * 2;
                bool v = (r < NK);
                int rs = v ? r : 0;
                cp16(base + OFF_BH + off, gBh + (size_t)rs * H + kt + k0, v);
                cp16(base + OFF_BL + off, gBl + (size_t)rs * H + kt + k0, v);
            }
        }
        asm volatile("cp.async.commit_group;\n" ::);
    };

    issue(0, 0);
    issue(BKG, 1);

    const int NIT = H / BKG;   // 32
    for (int i = 0; i < NIT; i++) {
        // Stage i must be complete. With up to 2 groups in flight, allow 1
        // outstanding (the i+1 prefetch) except on the last iteration.
        if (i < NIT - 1) asm volatile("cp.async.wait_group 1;\n" ::);
        else             asm volatile("cp.async.wait_group 0;\n" ::);
        __syncthreads();
        if (i + 2 < NIT) issue((i + 2) * BKG, (i + 2) % NSTAGE);

        const char* st = dsm + (i % NSTAGE) * STAGE_BYTES;
        const __nv_bfloat16* Ah = (const __nv_bfloat16*)(st + OFF_AH);
        const __nv_bfloat16* Al = (const __nv_bfloat16*)(st + OFF_AL);
        const __nv_bfloat16* Bh = (const __nv_bfloat16*)(st + OFF_BH);
        const __nv_bfloat16* Bl = (const __nv_bfloat16*)(st + OFF_BL);

        #pragma unroll
        for (int ks = 0; ks < BKG; ks += 16) {
            unsigned ah[2][4], al[2][4];
            #pragma unroll
            for (int mf = 0; mf < 2; mf++) {
                int r = wm * 32 + mf * 16 + qr;
                int c = ks + qp;
                ah[mf][0] = *reinterpret_cast<const unsigned*>(&Ah[r * BKP + c]);
                ah[mf][1] = *reinterpret_cast<const unsigned*>(&Ah[(r + 8) * BKP + c]);
                ah[mf][2] = *reinterpret_cast<const unsigned*>(&Ah[r * BKP + c + 8]);
                ah[mf][3] = *reinterpret_cast<const unsigned*>(&Ah[(r + 8) * BKP + c + 8]);
                al[mf][0] = *reinterpret_cast<const unsigned*>(&Al[r * BKP + c]);
                al[mf][1] = *reinterpret_cast<const unsigned*>(&Al[(r + 8) * BKP + c]);
                al[mf][2] = *reinterpret_cast<const unsigned*>(&Al[r * BKP + c + 8]);
                al[mf][3] = *reinterpret_cast<const unsigned*>(&Al[(r + 8) * BKP + c + 8]);
            }
            #pragma unroll
            for (int nf = 0; nf < 13; nf++) {
                int n = wn * 104 + nf * 8 + qr;
                int c = ks + qp;
                unsigned bh[2], bl[2];
                bh[0] = *reinterpret_cast<const unsigned*>(&Bh[n * BKP + c]);
                bh[1] = *reinterpret_cast<const unsigned*>(&Bh[n * BKP + c + 8]);
                bl[0] = *reinterpret_cast<const unsigned*>(&Bl[n * BKP + c]);
                bl[1] = *reinterpret_cast<const unsigned*>(&Bl[n * BKP + c + 8]);
                mma_bf16(acc[0][nf], ah[0], bh);
                mma_bf16(acc[1][nf], ah[1], bh);
                mma_bf16(acc[0][nf], ah[0], bl);
                mma_bf16(acc[1][nf], ah[1], bl);
                mma_bf16(acc[0][nf], al[0], bh);
                mma_bf16(acc[1][nf], al[1], bh);
            }
        }
    }

    // ---- fused epilogue: 4 chunks of 32 rows through smem ----
    __syncthreads();
    float* zs = (float*)dsm;                    // 32 x ZST floats = 26.9 KB
    const float NEGF = -3.402823466e38f;
    const float POSF =  3.402823466e38f;

    #pragma unroll 1
    for (int c = 0; c < 4; c++) {
        if (wm == c) {
            #pragma unroll
            for (int mf = 0; mf < 2; mf++)
                #pragma unroll
                for (int nf = 0; nf < 13; nf++) {
                    int r0  = mf * 16 + qr;
                    int col = wn * 104 + nf * 8 + qp;
                    *reinterpret_cast<float2*>(&zs[r0 * ZST + col]) =
                        make_float2(acc[mf][nf][0], acc[mf][nf][1]);
                    *reinterpret_cast<float2*>(&zs[(r0 + 8) * ZST + col]) =
                        make_float2(acc[mf][nf][2], acc[mf][nf][3]);
                }
        }
        __syncthreads();

        #pragma unroll
        for (int rr = 0; rr < 4; rr++) {
            int rl = warp * 4 + rr;
            int gq = tm * BM + c * 32 + rl;                 // q index in batch
            size_t orow = ((size_t)b * QQ + gq) * (NN + 1);

            float m = NEGF;
            if (lane < NN) {
                #pragma unroll
                for (int j = 0; j < KKK; j++)
                    m = fmaxf(m, zs[rl * ZST + lane * KKK + j]);
                out_logits[orow + lane] = m;
            }

            float mv = (lane < NN) ? m : POSF;
            #pragma unroll
            for (int o = 16; o; o >>= 1)
                mv = fminf(mv, __shfl_xor_sync(0xffffffffu, mv, o));
            if (lane == 0) out_logits[orow + NN] = mv - 1.0f;

            float v  = (lane < NN) ? m : NEGF;
            int  idx = lane;
            #pragma unroll
            for (int o = 16; o; o >>= 1) {
                float ov = __shfl_xor_sync(0xffffffffu, v, o);
                int   oi = __shfl_xor_sync(0xffffffffu, idx, o);
                if (ov > v || (ov == v && oi < idx)) { v = ov; idx = oi; }
            }
            if (lane == 0 && write_pred)
                out_pred[(size_t)b * QQ + gq] = (float)idx;
        }
        __syncthreads();
    }
}

// ---------------------------------------------------------------------------
extern "C" void kernel_launch(void* const* d_in, const int* in_sizes, int n_in,
                              void* d_out, int out_size) {
    const float* support = (const float*)d_in[0];
    const float* query   = (const float*)d_in[1];
    const float* gamma   = (const float*)d_in[2];
    const float* beta    = (const float*)d_in[3];
    float* out = (float*)d_out;

    // Opt-in to >48KB dynamic smem (idempotent; immediate API, not a stream op)
    cudaFuncSetAttribute(gemm_kernel,
                         cudaFuncAttributeMaxDynamicSharedMemorySize, SMEM_TOTAL);

    ln_kernel<<<SROWS / 8, 256>>>(support, gamma, beta, 0);
    ln_kernel<<<QROWS / 8, 256>>>(query,   gamma, beta, 1);

    const int logits_elems = BATCH * QQ * (NN + 1);  // 1,376,256
    const int write_pred   = (out_size >= logits_elems + QROWS) ? 1 : 0;

    dim3 grid(1, QQ / BM, BATCH);   // (1, 16, 32) = 512 CTAs
    gemm_kernel<<<grid, 256, SMEM_TOTAL>>>(out, out + logits_elems, write_pred);
}

// round 7
// speedup vs baseline: 3.1623x; 1.0303x over previous
#include <cuda_runtime.h>
#include <cuda_bf16.h>
#include <cstdint>

// Problem constants (fixed-shape benchmark)
#define H      1024
#define BATCH  32
#define NN     20        // N
#define KKK    10        // K (group size)
#define NK     200       // N*K
#define QQ     2048      // Q_total
#define SROWS  (BATCH * NK)   // 6400 support rows
#define QROWS  (BATCH * QQ)   // 65536 query rows

// Scratch (allocation-free: __device__ globals) — support LN only now
__device__ __nv_bfloat16 g_sh[(size_t)SROWS * H];   // support LN hi
__device__ __nv_bfloat16 g_sl[(size_t)SROWS * H];   // support LN lo

// ---------------------------------------------------------------------------
// LayerNorm for SUPPORT rows, warp-per-row: 8 warps/block = 8 rows/block.
// Emits split-bf16 (hi + residual lo).
// ---------------------------------------------------------------------------
__global__ __launch_bounds__(256) void ln_kernel(const float* __restrict__ x,
                          const float* __restrict__ gamma,
                          const float* __restrict__ beta) {
    const int lane = threadIdx.x & 31;
    const int warp = threadIdx.x >> 5;
    const int row  = blockIdx.x * 8 + warp;

    const float4* xr = reinterpret_cast<const float4*>(x) + (size_t)row * (H / 4);
    float4 a[8];
    #pragma unroll
    for (int i = 0; i < 8; i++) a[i] = xr[lane + i * 32];

    float s = 0.0f, ss = 0.0f;
    #pragma unroll
    for (int i = 0; i < 8; i++) {
        s  += (a[i].x + a[i].y) + (a[i].z + a[i].w);
        ss += fmaf(a[i].x, a[i].x, fmaf(a[i].y, a[i].y,
               fmaf(a[i].z, a[i].z, a[i].w * a[i].w)));
    }
    #pragma unroll
    for (int o = 16; o; o >>= 1) {
        s  += __shfl_xor_sync(0xffffffffu, s, o);
        ss += __shfl_xor_sync(0xffffffffu, ss, o);
    }
    const float mean = s * (1.0f / H);
    const float var  = ss * (1.0f / H) - mean * mean;
    const float rstd = rsqrtf(var + 1e-5f);

    uint2* dsth = reinterpret_cast<uint2*>(g_sh + (size_t)row * H);
    uint2* dstl = reinterpret_cast<uint2*>(g_sl + (size_t)row * H);
    const float4* g4 = reinterpret_cast<const float4*>(gamma);
    const float4* b4 = reinterpret_cast<const float4*>(beta);

    #pragma unroll
    for (int i = 0; i < 8; i++) {
        const int idx = lane + i * 32;
        float4 g  = g4[idx];
        float4 bb = b4[idx];
        float o0 = (a[i].x - mean) * rstd * g.x + bb.x;
        float o1 = (a[i].y - mean) * rstd * g.y + bb.y;
        float o2 = (a[i].z - mean) * rstd * g.z + bb.z;
        float o3 = (a[i].w - mean) * rstd * g.w + bb.w;

        __nv_bfloat162 h01 = __floats2bfloat162_rn(o0, o1);
        __nv_bfloat162 h23 = __floats2bfloat162_rn(o2, o3);
        uint2 hp;
        hp.x = *reinterpret_cast<unsigned*>(&h01);
        hp.y = *reinterpret_cast<unsigned*>(&h23);
        dsth[idx] = hp;

        __nv_bfloat162 l01 = __floats2bfloat162_rn(o0 - __bfloat162float(h01.x),
                                                   o1 - __bfloat162float(h01.y));
        __nv_bfloat162 l23 = __floats2bfloat162_rn(o2 - __bfloat162float(h23.x),
                                                   o3 - __bfloat162float(h23.y));
        uint2 lp;
        lp.x = *reinterpret_cast<unsigned*>(&l01);
        lp.y = *reinterpret_cast<unsigned*>(&l23);
        dstl[idx] = lp;
    }
}

// ---------------------------------------------------------------------------
// Fused kernel: query LN (stats prologue + on-the-fly split-bf16 convert)
// + tensor-core batched GEMM (split-bf16 x3) + max/min/argmax epilogue.
// CTA tile: BM=128 x BN=208, BK=32. 8 warps, warp tile 32x104.
// A-path: LDG fp32 (L2-resident after stats pass) -> convert -> smem (2 bufs)
// B-path: cp.async 3-stage ring of support hi/lo bf16.
// ---------------------------------------------------------------------------
#define BM   128
#define BN   208
#define BKG  32
#define BKP  40          // padded smem k-stride (bf16)

#define AH_B      (BM * BKP * 2)            // 10240
#define ABUF_B    (2 * AH_B)                // 20480 (Ah + Al)
#define OFF_BRING (2 * ABUF_B)              // 40960
#define BH_B      (BN * BKP * 2)            // 16640
#define BSTG_B    (2 * BH_B)                // 33280 (Bh + Bl)
#define OFF_GM    (OFF_BRING + 3 * BSTG_B)  // 140800
#define OFF_BT    (OFF_GM + 4096)           // 144896
#define OFF_ST    (OFF_BT + 4096)           // 148992 (mean[128], rstd[128])
#define SMEM_TOTAL (OFF_ST + 1024)          // 150016
#define ZST       210                       // epilogue smem row stride (floats)

__device__ __forceinline__ void cp16(uint32_t dst, const void* src, bool full) {
    int sz = full ? 16 : 0;
    asm volatile("cp.async.cg.shared.global [%0], [%1], 16, %2;\n"
                 :: "r"(dst), "l"(src), "r"(sz));
}

__device__ __forceinline__ void mma_bf16(float c[4],
                                         const unsigned a[4],
                                         const unsigned b[2]) {
    asm volatile(
        "mma.sync.aligned.m16n8k16.row.col.f32.bf16.bf16.f32 "
        "{%0,%1,%2,%3}, {%4,%5,%6,%7}, {%8,%9}, {%0,%1,%2,%3};\n"
        : "+f"(c[0]), "+f"(c[1]), "+f"(c[2]), "+f"(c[3])
        : "r"(a[0]), "r"(a[1]), "r"(a[2]), "r"(a[3]), "r"(b[0]), "r"(b[1]));
}

extern __shared__ char dsm[];

__global__ __launch_bounds__(256, 1) void gemm_kernel(const float* __restrict__ query,
                                                      const float* __restrict__ gamma,
                                                      const float* __restrict__ beta,
                                                      float* __restrict__ out_logits,
                                                      float* __restrict__ out_pred,
                                                      int write_pred) {
    const int b    = blockIdx.z;
    const int tm   = blockIdx.y;
    const int tid  = threadIdx.x;
    const int warp = tid >> 5, lane = tid & 31;
    const int wm = warp >> 1, wn = warp & 1;
    const int qr = lane >> 2;          // 0..7
    const int qp = (lane & 3) * 2;     // 0,2,4,6

    const float* gq = query + ((size_t)b * QQ + (size_t)tm * BM) * H;
    const __nv_bfloat16* gBh = g_sh + (size_t)b * NK * H;
    const __nv_bfloat16* gBl = g_sl + (size_t)b * NK * H;

    const uint32_t smem_u32 = (uint32_t)__cvta_generic_to_shared(dsm);

    // ---- prologue: gamma/beta -> smem; per-row LN stats -> smem ----
    {
        reinterpret_cast<float4*>(dsm + OFF_GM)[tid] =
            reinterpret_cast<const float4*>(gamma)[tid];
        reinterpret_cast<float4*>(dsm + OFF_BT)[tid] =
            reinterpret_cast<const float4*>(beta)[tid];

        float* smean = (float*)(dsm + OFF_ST);
        float* srstd = (float*)(dsm + OFF_ST + 512);
        #pragma unroll 1
        for (int rr = 0; rr < 16; rr++) {
            const int row = warp * 16 + rr;
            const float4* xr = reinterpret_cast<const float4*>(gq + (size_t)row * H);
            float s = 0.0f, ss = 0.0f;
            #pragma unroll
            for (int j = 0; j < 8; j++) {
                float4 a = xr[j * 32 + lane];
                s  += (a.x + a.y) + (a.z + a.w);
                ss += fmaf(a.x, a.x, fmaf(a.y, a.y, fmaf(a.z, a.z, a.w * a.w)));
            }
            #pragma unroll
            for (int o = 16; o; o >>= 1) {
                s  += __shfl_xor_sync(0xffffffffu, s, o);
                ss += __shfl_xor_sync(0xffffffffu, ss, o);
            }
            if (lane == 0) {
                float mean = s * (1.0f / H);
                float var  = ss * (1.0f / H) - mean * mean;
                smean[row] = mean;
                srstd[row] = rsqrtf(var + 1e-5f);
            }
        }
    }
    __syncthreads();

    // per-thread A assignment: row = tid>>1, k-half = (tid&1)*16
    const int arow = tid >> 1;
    const int ak0  = (tid & 1) * 16;
    const float amean = ((const float*)(dsm + OFF_ST))[arow];
    const float arstd = ((const float*)(dsm + OFF_ST + 512))[arow];
    const float* arow_p = gq + (size_t)arow * H;

    float acc[2][13][4];
    #pragma unroll
    for (int mf = 0; mf < 2; mf++)
        #pragma unroll
        for (int nf = 0; nf < 13; nf++)
            #pragma unroll
            for (int i = 0; i < 4; i++) acc[mf][nf][i] = 0.0f;

    // ---- B stage loader (cp.async) ----
    auto issueB = [&](int s, int buf) {
        const int kt = s * BKG;
        uint32_t base = smem_u32 + OFF_BRING + buf * BSTG_B;
        #pragma unroll
        for (int it = 0; it < 4; it++) {
            int idx = tid + it * 256;            // need < 832
            if (idx < 832) {
                int r = idx >> 2, k0 = (idx & 3) * 8;
                uint32_t off = (uint32_t)(r * BKP + k0) * 2;
                bool v = (r < NK);
                int rs = v ? r : 0;
                cp16(base + off,        gBh + (size_t)rs * H + kt + k0, v);
                cp16(base + BH_B + off, gBl + (size_t)rs * H + kt + k0, v);
            }
        }
        asm volatile("cp.async.commit_group;\n" ::);
    };

    // ---- A fetch (LDG fp32) + convert (LN affine -> split bf16 -> STS) ----
    float4 av[4];
    auto fetchA = [&](int s) {
        const float4* src = reinterpret_cast<const float4*>(arow_p + s * BKG + ak0);
        #pragma unroll
        for (int j = 0; j < 4; j++) av[j] = src[j];
    };
    auto convertA = [&](int s) {
        char* ab = dsm + (s & 1) * ABUF_B;
        uint2* dh = reinterpret_cast<uint2*>(ab + (arow * BKP + ak0) * 2);
        uint2* dl = reinterpret_cast<uint2*>(ab + AH_B + (arow * BKP + ak0) * 2);
        const float4* gg = reinterpret_cast<const float4*>(dsm + OFF_GM) + ((s * BKG + ak0) >> 2);
        const float4* bt = reinterpret_cast<const float4*>(dsm + OFF_BT) + ((s * BKG + ak0) >> 2);
        #pragma unroll
        for (int j = 0; j < 4; j++) {
            float4 x = av[j];
            float4 g = gg[j];
            float4 bb = bt[j];
            float o0 = (x.x - amean) * arstd * g.x + bb.x;
            float o1 = (x.y - amean) * arstd * g.y + bb.y;
            float o2 = (x.z - amean) * arstd * g.z + bb.z;
            float o3 = (x.w - amean) * arstd * g.w + bb.w;
            __nv_bfloat162 h01 = __floats2bfloat162_rn(o0, o1);
            __nv_bfloat162 h23 = __floats2bfloat162_rn(o2, o3);
            uint2 hp;
            hp.x = *reinterpret_cast<unsigned*>(&h01);
            hp.y = *reinterpret_cast<unsigned*>(&h23);
            dh[j] = hp;
            __nv_bfloat162 l01 = __floats2bfloat162_rn(o0 - __bfloat162float(h01.x),
                                                       o1 - __bfloat162float(h01.y));
            __nv_bfloat162 l23 = __floats2bfloat162_rn(o2 - __bfloat162float(h23.x),
                                                       o3 - __bfloat162float(h23.y));
            uint2 lp;
            lp.x = *reinterpret_cast<unsigned*>(&l01);
            lp.y = *reinterpret_cast<unsigned*>(&l23);
            dl[j] = lp;
        }
    };

    fetchA(0);
    issueB(0, 0);
    issueB(1, 1);
    convertA(0);
    fetchA(1);

    const int NIT = H / BKG;   // 32
    for (int i = 0; i < NIT; i++) {
        if (i < NIT - 1) asm volatile("cp.async.wait_group 1;\n" ::);
        else             asm volatile("cp.async.wait_group 0;\n" ::);
        __syncthreads();                      // A buf (i&1) + B stage i visible
        if (i + 2 < NIT) issueB(i + 2, (i + 2) % 3);

        const char* ab = dsm + (i & 1) * ABUF_B;
        const __nv_bfloat16* Ah = (const __nv_bfloat16*)(ab);
        const __nv_bfloat16* Al = (const __nv_bfloat16*)(ab + AH_B);
        const char* bst = dsm + OFF_BRING + (i % 3) * BSTG_B;
        const __nv_bfloat16* Bh = (const __nv_bfloat16*)(bst);
        const __nv_bfloat16* Bl = (const __nv_bfloat16*)(bst + BH_B);

        #pragma unroll
        for (int ks = 0; ks < BKG; ks += 16) {
            unsigned ah[2][4], al[2][4];
            #pragma unroll
            for (int mf = 0; mf < 2; mf++) {
                int r = wm * 32 + mf * 16 + qr;
                int c = ks + qp;
                ah[mf][0] = *reinterpret_cast<const unsigned*>(&Ah[r * BKP + c]);
                ah[mf][1] = *reinterpret_cast<const unsigned*>(&Ah[(r + 8) * BKP + c]);
                ah[mf][2] = *reinterpret_cast<const unsigned*>(&Ah[r * BKP + c + 8]);
                ah[mf][3] = *reinterpret_cast<const unsigned*>(&Ah[(r + 8) * BKP + c + 8]);
                al[mf][0] = *reinterpret_cast<const unsigned*>(&Al[r * BKP + c]);
                al[mf][1] = *reinterpret_cast<const unsigned*>(&Al[(r + 8) * BKP + c]);
                al[mf][2] = *reinterpret_cast<const unsigned*>(&Al[r * BKP + c + 8]);
                al[mf][3] = *reinterpret_cast<const unsigned*>(&Al[(r + 8) * BKP + c + 8]);
            }
            #pragma unroll
            for (int nf = 0; nf < 13; nf++) {
                int n = wn * 104 + nf * 8 + qr;
                int c = ks + qp;
                unsigned bh[2], bl[2];
                bh[0] = *reinterpret_cast<const unsigned*>(&Bh[n * BKP + c]);
                bh[1] = *reinterpret_cast<const unsigned*>(&Bh[n * BKP + c + 8]);
                bl[0] = *reinterpret_cast<const unsigned*>(&Bl[n * BKP + c]);
                bl[1] = *reinterpret_cast<const unsigned*>(&Bl[n * BKP + c + 8]);
                mma_bf16(acc[0][nf], ah[0], bh);
                mma_bf16(acc[1][nf], ah[1], bh);
                mma_bf16(acc[0][nf], ah[0], bl);
                mma_bf16(acc[1][nf], ah[1], bl);
                mma_bf16(acc[0][nf], al[0], bh);
                mma_bf16(acc[1][nf], al[1], bh);
            }
        }

        // prepare next A stage (writes buf (i+1)&1, not read until next sync)
        if (i + 1 < NIT) {
            convertA(i + 1);
            if (i + 2 < NIT) fetchA(i + 2);
        }
    }

    // ---- fused epilogue: all 128 rows staged at once ----
    __syncthreads();
    float* zs = (float*)dsm;                    // 128 x ZST floats = 107.5 KB
    #pragma unroll
    for (int mf = 0; mf < 2; mf++)
        #pragma unroll
        for (int nf = 0; nf < 13; nf++) {
            int r0  = wm * 32 + mf * 16 + qr;
            int col = wn * 104 + nf * 8 + qp;
            *reinterpret_cast<float2*>(&zs[r0 * ZST + col]) =
                make_float2(acc[mf][nf][0], acc[mf][nf][1]);
            *reinterpret_cast<float2*>(&zs[(r0 + 8) * ZST + col]) =
                make_float2(acc[mf][nf][2], acc[mf][nf][3]);
        }
    __syncthreads();

    const float NEGF = -3.402823466e38f;
    const float POSF =  3.402823466e38f;
    #pragma unroll 1
    for (int rr = 0; rr < 16; rr++) {
        int rl = warp * 16 + rr;
        int gq_ = tm * BM + rl;
        size_t orow = ((size_t)b * QQ + gq_) * (NN + 1);

        float m = NEGF;
        if (lane < NN) {
            #pragma unroll
            for (int j = 0; j < KKK; j++)
                m = fmaxf(m, zs[rl * ZST + lane * KKK + j]);
            out_logits[orow + lane] = m;
        }

        float mv = (lane < NN) ? m : POSF;
        #pragma unroll
        for (int o = 16; o; o >>= 1)
            mv = fminf(mv, __shfl_xor_sync(0xffffffffu, mv, o));
        if (lane == 0) out_logits[orow + NN] = mv - 1.0f;

        float v  = (lane < NN) ? m : NEGF;
        int  idx = lane;
        #pragma unroll
        for (int o = 16; o; o >>= 1) {
            float ov = __shfl_xor_sync(0xffffffffu, v, o);
            int   oi = __shfl_xor_sync(0xffffffffu, idx, o);
            if (ov > v || (ov == v && oi < idx)) { v = ov; idx = oi; }
        }
        if (lane == 0 && write_pred)
            out_pred[(size_t)b * QQ + gq_] = (float)idx;
    }
}

// ---------------------------------------------------------------------------
extern "C" void kernel_launch(void* const* d_in, const int* in_sizes, int n_in,
                              void* d_out, int out_size) {
    const float* support = (const float*)d_in[0];
    const float* query   = (const float*)d_in[1];
    const float* gamma   = (const float*)d_in[2];
    const float* beta    = (const float*)d_in[3];
    float* out = (float*)d_out;

    cudaFuncSetAttribute(gemm_kernel,
                         cudaFuncAttributeMaxDynamicSharedMemorySize, SMEM_TOTAL);

    ln_kernel<<<SROWS / 8, 256>>>(support, gamma, beta);

    const int logits_elems = BATCH * QQ * (NN + 1);  // 1,376,256
    const int write_pred   = (out_size >= logits_elems + QROWS) ? 1 : 0;

    dim3 grid(1, QQ / BM, BATCH);   // (1, 16, 32) = 512 CTAs
    gemm_kernel<<<grid, 256, SMEM_TOTAL>>>(query, gamma, beta,
                                           out, out + logits_elems, write_pred);
}

// round 8
// speedup vs baseline: 3.2159x; 1.0170x over previous
#include <cuda_runtime.h>
#include <cuda_bf16.h>
#include <cstdint>

// Problem constants (fixed-shape benchmark)
#define H      1024
#define BATCH  32
#define NN     20        // N
#define KKK    10        // K (group size)
#define NK     200       // N*K
#define QQ     2048      // Q_total
#define SROWS  (BATCH * NK)   // 6400 support rows
#define QROWS  (BATCH * QQ)   // 65536 query rows

// Scratch (allocation-free: __device__ globals) — support LN only
__device__ __nv_bfloat16 g_sh[(size_t)SROWS * H];   // support LN hi
__device__ __nv_bfloat16 g_sl[(size_t)SROWS * H];   // support LN lo

// ---------------------------------------------------------------------------
// LayerNorm for SUPPORT rows, warp-per-row: 8 warps/block = 8 rows/block.
// ---------------------------------------------------------------------------
__global__ __launch_bounds__(256) void ln_kernel(const float* __restrict__ x,
                          const float* __restrict__ gamma,
                          const float* __restrict__ beta) {
    const int lane = threadIdx.x & 31;
    const int warp = threadIdx.x >> 5;
    const int row  = blockIdx.x * 8 + warp;

    const float4* xr = reinterpret_cast<const float4*>(x) + (size_t)row * (H / 4);
    float4 a[8];
    #pragma unroll
    for (int i = 0; i < 8; i++) a[i] = xr[lane + i * 32];

    float s = 0.0f, ss = 0.0f;
    #pragma unroll
    for (int i = 0; i < 8; i++) {
        s  += (a[i].x + a[i].y) + (a[i].z + a[i].w);
        ss += fmaf(a[i].x, a[i].x, fmaf(a[i].y, a[i].y,
               fmaf(a[i].z, a[i].z, a[i].w * a[i].w)));
    }
    #pragma unroll
    for (int o = 16; o; o >>= 1) {
        s  += __shfl_xor_sync(0xffffffffu, s, o);
        ss += __shfl_xor_sync(0xffffffffu, ss, o);
    }
    const float mean = s * (1.0f / H);
    const float var  = ss * (1.0f / H) - mean * mean;
    const float rstd = rsqrtf(var + 1e-5f);

    uint2* dsth = reinterpret_cast<uint2*>(g_sh + (size_t)row * H);
    uint2* dstl = reinterpret_cast<uint2*>(g_sl + (size_t)row * H);
    const float4* g4 = reinterpret_cast<const float4*>(gamma);
    const float4* b4 = reinterpret_cast<const float4*>(beta);

    #pragma unroll
    for (int i = 0; i < 8; i++) {
        const int idx = lane + i * 32;
        float4 g  = g4[idx];
        float4 bb = b4[idx];
        float o0 = (a[i].x - mean) * rstd * g.x + bb.x;
        float o1 = (a[i].y - mean) * rstd * g.y + bb.y;
        float o2 = (a[i].z - mean) * rstd * g.z + bb.z;
        float o3 = (a[i].w - mean) * rstd * g.w + bb.w;

        __nv_bfloat162 h01 = __floats2bfloat162_rn(o0, o1);
        __nv_bfloat162 h23 = __floats2bfloat162_rn(o2, o3);
        uint2 hp;
        hp.x = *reinterpret_cast<unsigned*>(&h01);
        hp.y = *reinterpret_cast<unsigned*>(&h23);
        dsth[idx] = hp;

        __nv_bfloat162 l01 = __floats2bfloat162_rn(o0 - __bfloat162float(h01.x),
                                                   o1 - __bfloat162float(h01.y));
        __nv_bfloat162 l23 = __floats2bfloat162_rn(o2 - __bfloat162float(h23.x),
                                                   o3 - __bfloat162float(h23.y));
        uint2 lp;
        lp.x = *reinterpret_cast<unsigned*>(&l01);
        lp.y = *reinterpret_cast<unsigned*>(&l23);
        dstl[idx] = lp;
    }
}

// ---------------------------------------------------------------------------
// Fused kernel: query LN (stats prologue + on-the-fly split-bf16 convert)
// + tensor-core batched GEMM (split-bf16 x3) + max/min/argmax epilogue.
// CTA tile: BM=128 x BN=208, BK=32. 512 threads / 16 warps, warp tile 16x104.
// ---------------------------------------------------------------------------
#define BM   128
#define BN   208
#define BKG  32
#define BKP  40          // padded smem k-stride (bf16)
#define NTHR 512

#define AH_B      (BM * BKP * 2)            // 10240
#define ABUF_B    (2 * AH_B)                // 20480 (Ah + Al)
#define OFF_BRING (2 * ABUF_B)              // 40960
#define BH_B      (BN * BKP * 2)            // 16640
#define BSTG_B    (2 * BH_B)                // 33280 (Bh + Bl)
#define OFF_GM    (OFF_BRING + 3 * BSTG_B)  // 140800
#define OFF_BT    (OFF_GM + 4096)           // 144896
#define OFF_ST    (OFF_BT + 4096)           // 148992 (mean[128], rstd[128])
#define SMEM_TOTAL (OFF_ST + 1024)          // 150016
#define ZST       210                       // epilogue smem row stride (floats)

__device__ __forceinline__ void cp16(uint32_t dst, const void* src, bool full) {
    int sz = full ? 16 : 0;
    asm volatile("cp.async.cg.shared.global [%0], [%1], 16, %2;\n"
                 :: "r"(dst), "l"(src), "r"(sz));
}

__device__ __forceinline__ void mma_bf16(float c[4],
                                         const unsigned a[4],
                                         const unsigned b[2]) {
    asm volatile(
        "mma.sync.aligned.m16n8k16.row.col.f32.bf16.bf16.f32 "
        "{%0,%1,%2,%3}, {%4,%5,%6,%7}, {%8,%9}, {%0,%1,%2,%3};\n"
        : "+f"(c[0]), "+f"(c[1]), "+f"(c[2]), "+f"(c[3])
        : "r"(a[0]), "r"(a[1]), "r"(a[2]), "r"(a[3]), "r"(b[0]), "r"(b[1]));
}

extern __shared__ char dsm[];

__global__ __launch_bounds__(NTHR, 1) void gemm_kernel(const float* __restrict__ query,
                                                       const float* __restrict__ gamma,
                                                       const float* __restrict__ beta,
                                                       float* __restrict__ out_logits,
                                                       float* __restrict__ out_pred,
                                                       int write_pred) {
    const int b    = blockIdx.z;
    const int tm   = blockIdx.y;
    const int tid  = threadIdx.x;
    const int warp = tid >> 5, lane = tid & 31;
    const int wm = warp >> 1, wn = warp & 1;   // 8 m-warps x 2 n-warps
    const int qr = lane >> 2;          // 0..7
    const int qp = (lane & 3) * 2;     // 0,2,4,6

    const float* gq = query + ((size_t)b * QQ + (size_t)tm * BM) * H;
    const __nv_bfloat16* gBh = g_sh + (size_t)b * NK * H;
    const __nv_bfloat16* gBl = g_sl + (size_t)b * NK * H;

    const uint32_t smem_u32 = (uint32_t)__cvta_generic_to_shared(dsm);

    // ---- prologue: gamma/beta -> smem; per-row LN stats -> smem ----
    {
        if (tid < 256) {
            reinterpret_cast<float4*>(dsm + OFF_GM)[tid] =
                reinterpret_cast<const float4*>(gamma)[tid];
            reinterpret_cast<float4*>(dsm + OFF_BT)[tid] =
                reinterpret_cast<const float4*>(beta)[tid];
        }
        float* smean = (float*)(dsm + OFF_ST);
        float* srstd = (float*)(dsm + OFF_ST + 512);
        #pragma unroll 1
        for (int rr = 0; rr < 8; rr++) {
            const int row = warp * 8 + rr;
            const float4* xr = reinterpret_cast<const float4*>(gq + (size_t)row * H);
            float s = 0.0f, ss = 0.0f;
            #pragma unroll
            for (int j = 0; j < 8; j++) {
                float4 a = xr[j * 32 + lane];
                s  += (a.x + a.y) + (a.z + a.w);
                ss += fmaf(a.x, a.x, fmaf(a.y, a.y, fmaf(a.z, a.z, a.w * a.w)));
            }
            #pragma unroll
            for (int o = 16; o; o >>= 1) {
                s  += __shfl_xor_sync(0xffffffffu, s, o);
                ss += __shfl_xor_sync(0xffffffffu, ss, o);
            }
            if (lane == 0) {
                float mean = s * (1.0f / H);
                float var  = ss * (1.0f / H) - mean * mean;
                smean[row] = mean;
                srstd[row] = rsqrtf(var + 1e-5f);
            }
        }
    }
    __syncthreads();

    // per-thread A assignment: row = tid>>2, k-eighth = (tid&3)*8
    const int arow = tid >> 2;
    const int ak0  = (tid & 3) * 8;
    const float amean = ((const float*)(dsm + OFF_ST))[arow];
    const float arstd = ((const float*)(dsm + OFF_ST + 512))[arow];
    const float* arow_p = gq + (size_t)arow * H;

    float acc[13][4];
    #pragma unroll
    for (int nf = 0; nf < 13; nf++)
        #pragma unroll
        for (int i = 0; i < 4; i++) acc[nf][i] = 0.0f;

    // ---- B stage loader (cp.async) ----
    auto issueB = [&](int s, int buf) {
        const int kt = s * BKG;
        uint32_t base = smem_u32 + OFF_BRING + buf * BSTG_B;
        #pragma unroll
        for (int it = 0; it < 2; it++) {
            int idx = tid + it * NTHR;           // need < 832
            if (idx < 832) {
                int r = idx >> 2, k0 = (idx & 3) * 8;
                uint32_t off = (uint32_t)(r * BKP + k0) * 2;
                bool v = (r < NK);
                int rs = v ? r : 0;
                cp16(base + off,        gBh + (size_t)rs * H + kt + k0, v);
                cp16(base + BH_B + off, gBl + (size_t)rs * H + kt + k0, v);
            }
        }
        asm volatile("cp.async.commit_group;\n" ::);
    };

    // ---- A fetch (LDG fp32) + convert (LN affine -> split bf16 -> STS) ----
    float4 av[2];
    auto fetchA = [&](int s) {
        const float4* src = reinterpret_cast<const float4*>(arow_p + s * BKG + ak0);
        av[0] = src[0];
        av[1] = src[1];
    };
    auto convertA = [&](int s) {
        char* ab = dsm + (s & 1) * ABUF_B;
        uint2* dh = reinterpret_cast<uint2*>(ab + (arow * BKP + ak0) * 2);
        uint2* dl = reinterpret_cast<uint2*>(ab + AH_B + (arow * BKP + ak0) * 2);
        const float4* gg = reinterpret_cast<const float4*>(dsm + OFF_GM) + ((s * BKG + ak0) >> 2);
        const float4* bt = reinterpret_cast<const float4*>(dsm + OFF_BT) + ((s * BKG + ak0) >> 2);
        #pragma unroll
        for (int j = 0; j < 2; j++) {
            float4 x = av[j];
            float4 g = gg[j];
            float4 bb = bt[j];
            float o0 = (x.x - amean) * arstd * g.x + bb.x;
            float o1 = (x.y - amean) * arstd * g.y + bb.y;
            float o2 = (x.z - amean) * arstd * g.z + bb.z;
            float o3 = (x.w - amean) * arstd * g.w + bb.w;
            __nv_bfloat162 h01 = __floats2bfloat162_rn(o0, o1);
            __nv_bfloat162 h23 = __floats2bfloat162_rn(o2, o3);
            uint2 hp;
            hp.x = *reinterpret_cast<unsigned*>(&h01);
            hp.y = *reinterpret_cast<unsigned*>(&h23);
            dh[j] = hp;
            __nv_bfloat162 l01 = __floats2bfloat162_rn(o0 - __bfloat162float(h01.x),
                                                       o1 - __bfloat162float(h01.y));
            __nv_bfloat162 l23 = __floats2bfloat162_rn(o2 - __bfloat162float(h23.x),
                                                       o3 - __bfloat162float(h23.y));
            uint2 lp;
            lp.x = *reinterpret_cast<unsigned*>(&l01);
            lp.y = *reinterpret_cast<unsigned*>(&l23);
            dl[j] = lp;
        }
    };

    fetchA(0);
    issueB(0, 0);
    issueB(1, 1);
    convertA(0);
    fetchA(1);

    const int NIT = H / BKG;   // 32
    for (int i = 0; i < NIT; i++) {
        if (i < NIT - 1) asm volatile("cp.async.wait_group 1;\n" ::);
        else             asm volatile("cp.async.wait_group 0;\n" ::);
        __syncthreads();                      // A buf (i&1) + B stage i visible
        if (i + 2 < NIT) issueB(i + 2, (i + 2) % 3);

        const char* ab = dsm + (i & 1) * ABUF_B;
        const __nv_bfloat16* Ah = (const __nv_bfloat16*)(ab);
        const __nv_bfloat16* Al = (const __nv_bfloat16*)(ab + AH_B);
        const char* bst = dsm + OFF_BRING + (i % 3) * BSTG_B;
        const __nv_bfloat16* Bh = (const __nv_bfloat16*)(bst);
        const __nv_bfloat16* Bl = (const __nv_bfloat16*)(bst + BH_B);

        #pragma unroll
        for (int ks = 0; ks < BKG; ks += 16) {
            unsigned ah[4], al[4];
            {
                int r = wm * 16 + qr;
                int c = ks + qp;
                ah[0] = *reinterpret_cast<const unsigned*>(&Ah[r * BKP + c]);
                ah[1] = *reinterpret_cast<const unsigned*>(&Ah[(r + 8) * BKP + c]);
                ah[2] = *reinterpret_cast<const unsigned*>(&Ah[r * BKP + c + 8]);
                ah[3] = *reinterpret_cast<const unsigned*>(&Ah[(r + 8) * BKP + c + 8]);
                al[0] = *reinterpret_cast<const unsigned*>(&Al[r * BKP + c]);
                al[1] = *reinterpret_cast<const unsigned*>(&Al[(r + 8) * BKP + c]);
                al[2] = *reinterpret_cast<const unsigned*>(&Al[r * BKP + c + 8]);
                al[3] = *reinterpret_cast<const unsigned*>(&Al[(r + 8) * BKP + c + 8]);
            }
            #pragma unroll
            for (int nf = 0; nf < 13; nf++) {
                int n = wn * 104 + nf * 8 + qr;
                int c = ks + qp;
                unsigned bh[2], bl[2];
                bh[0] = *reinterpret_cast<const unsigned*>(&Bh[n * BKP + c]);
                bh[1] = *reinterpret_cast<const unsigned*>(&Bh[n * BKP + c + 8]);
                bl[0] = *reinterpret_cast<const unsigned*>(&Bl[n * BKP + c]);
                bl[1] = *reinterpret_cast<const unsigned*>(&Bl[n * BKP + c + 8]);
                mma_bf16(acc[nf], ah, bh);
                mma_bf16(acc[nf], ah, bl);
                mma_bf16(acc[nf], al, bh);
            }
        }

        // prepare next A stage (writes buf (i+1)&1, not read until next sync)
        if (i + 1 < NIT) {
            convertA(i + 1);
            if (i + 2 < NIT) fetchA(i + 2);
        }
    }

    // ---- fused epilogue: all 128 rows staged at once ----
    __syncthreads();
    float* zs = (float*)dsm;                    // 128 x ZST floats = 107.5 KB
    #pragma unroll
    for (int nf = 0; nf < 13; nf++) {
        int r0  = wm * 16 + qr;
        int col = wn * 104 + nf * 8 + qp;
        *reinterpret_cast<float2*>(&zs[r0 * ZST + col]) =
            make_float2(acc[nf][0], acc[nf][1]);
        *reinterpret_cast<float2*>(&zs[(r0 + 8) * ZST + col]) =
            make_float2(acc[nf][2], acc[nf][3]);
    }
    __syncthreads();

    const float NEGF = -3.402823466e38f;
    const float POSF =  3.402823466e38f;
    #pragma unroll 1
    for (int rr = 0; rr < 8; rr++) {
        int rl = warp * 8 + rr;
        int gq_ = tm * BM + rl;
        size_t orow = ((size_t)b * QQ + gq_) * (NN + 1);

        float m = NEGF;
        if (lane < NN) {
            #pragma unroll
            for (int j = 0; j < KKK; j++)
                m = fmaxf(m, zs[rl * ZST + lane * KKK + j]);
            out_logits[orow + lane] = m;
        }

        float mv = (lane < NN) ? m : POSF;
        #pragma unroll
        for (int o = 16; o; o >>= 1)
            mv = fminf(mv, __shfl_xor_sync(0xffffffffu, mv, o));
        if (lane == 0) out_logits[orow + NN] = mv - 1.0f;

        float v  = (lane < NN) ? m : NEGF;
        int  idx = lane;
        #pragma unroll
        for (int o = 16; o; o >>= 1) {
            float ov = __shfl_xor_sync(0xffffffffu, v, o);
            int   oi = __shfl_xor_sync(0xffffffffu, idx, o);
            if (ov > v || (ov == v && oi < idx)) { v = ov; idx = oi; }
        }
        if (lane == 0 && write_pred)
            out_pred[(size_t)b * QQ + gq_] = (float)idx;
    }
}

// ---------------------------------------------------------------------------
extern "C" void kernel_launch(void* const* d_in, const int* in_sizes, int n_in,
                              void* d_out, int out_size) {
    const float* support = (const float*)d_in[0];
    const float* query   = (const float*)d_in[1];
    const float* gamma   = (const float*)d_in[2];
    const float* beta    = (const float*)d_in[3];
    float* out = (float*)d_out;

    cudaFuncSetAttribute(gemm_kernel,
                         cudaFuncAttributeMaxDynamicSharedMemorySize, SMEM_TOTAL);

    ln_kernel<<<SROWS / 8, 256>>>(support, gamma, beta);

    const int logits_elems = BATCH * QQ * (NN + 1);  // 1,376,256
    const int write_pred   = (out_size >= logits_elems + QROWS) ? 1 : 0;

    dim3 grid(1, QQ / BM, BATCH);   // (1, 16, 32) = 512 CTAs
    gemm_kernel<<<grid, NTHR, SMEM_TOTAL>>>(query, gamma, beta,
                                            out, out + logits_elems, write_pred);
}

// round 9
// speedup vs baseline: 3.4240x; 1.0647x over previous
#include <cuda_runtime.h>
#include <cuda_bf16.h>
#include <cstdint>

// Problem constants (fixed-shape benchmark)
#define H      1024
#define BATCH  32
#define NN     20        // N
#define KKK    10        // K (group size)
#define NK     200       // N*K
#define QQ     2048      // Q_total
#define SROWS  (BATCH * NK)   // 6400 support rows
#define QROWS  (BATCH * QQ)   // 65536 query rows

// Scratch (allocation-free: __device__ globals) — support LN only
__device__ __nv_bfloat16 g_sh[(size_t)SROWS * H];   // support LN hi
__device__ __nv_bfloat16 g_sl[(size_t)SROWS * H];   // support LN lo

// ---------------------------------------------------------------------------
// LayerNorm for SUPPORT rows, warp-per-row: 8 warps/block = 8 rows/block.
// ---------------------------------------------------------------------------
__global__ __launch_bounds__(256) void ln_kernel(const float* __restrict__ x,
                          const float* __restrict__ gamma,
                          const float* __restrict__ beta) {
    const int lane = threadIdx.x & 31;
    const int warp = threadIdx.x >> 5;
    const int row  = blockIdx.x * 8 + warp;

    const float4* xr = reinterpret_cast<const float4*>(x) + (size_t)row * (H / 4);
    float4 a[8];
    #pragma unroll
    for (int i = 0; i < 8; i++) a[i] = xr[lane + i * 32];

    float s = 0.0f, ss = 0.0f;
    #pragma unroll
    for (int i = 0; i < 8; i++) {
        s  += (a[i].x + a[i].y) + (a[i].z + a[i].w);
        ss += fmaf(a[i].x, a[i].x, fmaf(a[i].y, a[i].y,
               fmaf(a[i].z, a[i].z, a[i].w * a[i].w)));
    }
    #pragma unroll
    for (int o = 16; o; o >>= 1) {
        s  += __shfl_xor_sync(0xffffffffu, s, o);
        ss += __shfl_xor_sync(0xffffffffu, ss, o);
    }
    const float mean = s * (1.0f / H);
    const float var  = ss * (1.0f / H) - mean * mean;
    const float rstd = rsqrtf(var + 1e-5f);

    uint2* dsth = reinterpret_cast<uint2*>(g_sh + (size_t)row * H);
    uint2* dstl = reinterpret_cast<uint2*>(g_sl + (size_t)row * H);
    const float4* g4 = reinterpret_cast<const float4*>(gamma);
    const float4* b4 = reinterpret_cast<const float4*>(beta);

    #pragma unroll
    for (int i = 0; i < 8; i++) {
        const int idx = lane + i * 32;
        float4 g  = g4[idx];
        float4 bb = b4[idx];
        float o0 = (a[i].x - mean) * rstd * g.x + bb.x;
        float o1 = (a[i].y - mean) * rstd * g.y + bb.y;
        float o2 = (a[i].z - mean) * rstd * g.z + bb.z;
        float o3 = (a[i].w - mean) * rstd * g.w + bb.w;

        __nv_bfloat162 h01 = __floats2bfloat162_rn(o0, o1);
        __nv_bfloat162 h23 = __floats2bfloat162_rn(o2, o3);
        uint2 hp;
        hp.x = *reinterpret_cast<unsigned*>(&h01);
        hp.y = *reinterpret_cast<unsigned*>(&h23);
        dsth[idx] = hp;

        __nv_bfloat162 l01 = __floats2bfloat162_rn(o0 - __bfloat162float(h01.x),
                                                   o1 - __bfloat162float(h01.y));
        __nv_bfloat162 l23 = __floats2bfloat162_rn(o2 - __bfloat162float(h23.x),
                                                   o3 - __bfloat162float(h23.y));
        uint2 lp;
        lp.x = *reinterpret_cast<unsigned*>(&l01);
        lp.y = *reinterpret_cast<unsigned*>(&l23);
        dstl[idx] = lp;
    }
}

// ---------------------------------------------------------------------------
// Fused kernel: query LN (stats prologue + on-the-fly split-bf16 convert)
// + tensor-core batched GEMM (split-bf16 x3) + max/min/argmax epilogue.
// CTA tile: BM=128 x BN=208, BK=32. 512 threads / 16 warps, warp tile 16x104.
// Fragment loads via ldmatrix (x4/x2) — 16 LDSM/warp/kstep vs 60 LDS before.
// ---------------------------------------------------------------------------
#define BM   128
#define BN   208
#define BKG  32
#define BKP  40          // padded smem k-stride (bf16); 80B rows: 8-row x 16B
                         // LDSM phases hit 32 distinct banks (80=16*5, 5 odd)
#define NTHR 512

#define AH_B      (BM * BKP * 2)            // 10240
#define ABUF_B    (2 * AH_B)                // 20480 (Ah + Al)
#define OFF_BRING (2 * ABUF_B)              // 40960
#define BH_B      (BN * BKP * 2)            // 16640
#define BSTG_B    (2 * BH_B)                // 33280 (Bh + Bl)
#define OFF_GM    (OFF_BRING + 3 * BSTG_B)  // 140800
#define OFF_BT    (OFF_GM + 4096)           // 144896
#define OFF_ST    (OFF_BT + 4096)           // 148992 (mean[128], rstd[128])
#define SMEM_TOTAL (OFF_ST + 1024)          // 150016
#define ZST       210                       // epilogue smem row stride (floats)

__device__ __forceinline__ void cp16(uint32_t dst, const void* src, bool full) {
    int sz = full ? 16 : 0;
    asm volatile("cp.async.cg.shared.global [%0], [%1], 16, %2;\n"
                 :: "r"(dst), "l"(src), "r"(sz));
}

__device__ __forceinline__ void mma_bf16(float c[4],
                                         const unsigned a[4],
                                         unsigned b0, unsigned b1) {
    asm volatile(
        "mma.sync.aligned.m16n8k16.row.col.f32.bf16.bf16.f32 "
        "{%0,%1,%2,%3}, {%4,%5,%6,%7}, {%8,%9}, {%0,%1,%2,%3};\n"
        : "+f"(c[0]), "+f"(c[1]), "+f"(c[2]), "+f"(c[3])
        : "r"(a[0]), "r"(a[1]), "r"(a[2]), "r"(a[3]), "r"(b0), "r"(b1));
}

__device__ __forceinline__ void ldsm_x4(unsigned r[4], uint32_t addr) {
    asm volatile("ldmatrix.sync.aligned.m8n8.x4.shared.b16 {%0,%1,%2,%3}, [%4];"
                 : "=r"(r[0]), "=r"(r[1]), "=r"(r[2]), "=r"(r[3]) : "r"(addr));
}
__device__ __forceinline__ void ldsm_x2(unsigned r[2], uint32_t addr) {
    asm volatile("ldmatrix.sync.aligned.m8n8.x2.shared.b16 {%0,%1}, [%2];"
                 : "=r"(r[0]), "=r"(r[1]) : "r"(addr));
}

extern __shared__ char dsm[];

__global__ __launch_bounds__(NTHR, 1) void gemm_kernel(const float* __restrict__ query,
                                                       const float* __restrict__ gamma,
                                                       const float* __restrict__ beta,
                                                       float* __restrict__ out_logits,
                                                       float* __restrict__ out_pred,
                                                       int write_pred) {
    const int b    = blockIdx.z;
    const int tm   = blockIdx.y;
    const int tid  = threadIdx.x;
    const int warp = tid >> 5, lane = tid & 31;
    const int wm = warp >> 1, wn = warp & 1;   // 8 m-warps x 2 n-warps
    const int qr = lane >> 2;          // 0..7
    const int qp = (lane & 3) * 2;     // 0,2,4,6

    const float* gq = query + ((size_t)b * QQ + (size_t)tm * BM) * H;
    const __nv_bfloat16* gBh = g_sh + (size_t)b * NK * H;
    const __nv_bfloat16* gBl = g_sl + (size_t)b * NK * H;

    const uint32_t smem_u32 = (uint32_t)__cvta_generic_to_shared(dsm);

    // ---- prologue: gamma/beta -> smem; per-row LN stats -> smem ----
    {
        if (tid < 256) {
            reinterpret_cast<float4*>(dsm + OFF_GM)[tid] =
                reinterpret_cast<const float4*>(gamma)[tid];
            reinterpret_cast<float4*>(dsm + OFF_BT)[tid] =
                reinterpret_cast<const float4*>(beta)[tid];
        }
        float* smean = (float*)(dsm + OFF_ST);
        float* srstd = (float*)(dsm + OFF_ST + 512);
        #pragma unroll 1
        for (int rr = 0; rr < 8; rr++) {
            const int row = warp * 8 + rr;
            const float4* xr = reinterpret_cast<const float4*>(gq + (size_t)row * H);
            float s = 0.0f, ss = 0.0f;
            #pragma unroll
            for (int j = 0; j < 8; j++) {
                float4 a = xr[j * 32 + lane];
                s  += (a.x + a.y) + (a.z + a.w);
                ss += fmaf(a.x, a.x, fmaf(a.y, a.y, fmaf(a.z, a.z, a.w * a.w)));
            }
            #pragma unroll
            for (int o = 16; o; o >>= 1) {
                s  += __shfl_xor_sync(0xffffffffu, s, o);
                ss += __shfl_xor_sync(0xffffffffu, ss, o);
            }
            if (lane == 0) {
                float mean = s * (1.0f / H);
                float var  = ss * (1.0f / H) - mean * mean;
                smean[row] = mean;
                srstd[row] = rsqrtf(var + 1e-5f);
            }
        }
    }
    __syncthreads();

    // per-thread A assignment: row = tid>>2, k-eighth = (tid&3)*8
    const int arow = tid >> 2;
    const int ak0  = (tid & 3) * 8;
    const float amean = ((const float*)(dsm + OFF_ST))[arow];
    const float arstd = ((const float*)(dsm + OFF_ST + 512))[arow];
    const float* arow_p = gq + (size_t)arow * H;

    // ldmatrix lane->tile-row/col mappings
    // A x4 tiles: (m0,k0),(m8,k0),(m0,k8),(m8,k8) -> a0..a3
    const int a_lrow = wm * 16 + (lane & 7) + ((lane >> 3) & 1) * 8;
    const int a_lcol = ((lane >> 4) & 1) * 8;
    // B x4 tiles: (n0,k0),(n0,k8),(n8,k0),(n8,k8) -> nf0{r0,r1}, nf1{r2,r3}
    const int b_lrow = wn * 104 + (lane & 7) + ((lane >> 4) & 1) * 8;
    const int b_lcol = ((lane >> 3) & 1) * 8;
    // B x2 tail (lanes 0-15): (n0,k0),(n0,k8)
    const int t_lrow = wn * 104 + 96 + (lane & 7);
    const int t_lcol = ((lane >> 3) & 1) * 8;

    float acc[13][4];
    #pragma unroll
    for (int nf = 0; nf < 13; nf++)
        #pragma unroll
        for (int i = 0; i < 4; i++) acc[nf][i] = 0.0f;

    // ---- B stage loader (cp.async) ----
    auto issueB = [&](int s, int buf) {
        const int kt = s * BKG;
        uint32_t base = smem_u32 + OFF_BRING + buf * BSTG_B;
        #pragma unroll
        for (int it = 0; it < 2; it++) {
            int idx = tid + it * NTHR;           // need < 832
            if (idx < 832) {
                int r = idx >> 2, k0 = (idx & 3) * 8;
                uint32_t off = (uint32_t)(r * BKP + k0) * 2;
                bool v = (r < NK);
                int rs = v ? r : 0;
                cp16(base + off,        gBh + (size_t)rs * H + kt + k0, v);
                cp16(base + BH_B + off, gBl + (size_t)rs * H + kt + k0, v);
            }
        }
        asm volatile("cp.async.commit_group;\n" ::);
    };

    // ---- A fetch (LDG fp32) + convert (LN affine -> split bf16 -> STS) ----
    float4 av[2];
    auto fetchA = [&](int s) {
        const float4* src = reinterpret_cast<const float4*>(arow_p + s * BKG + ak0);
        av[0] = src[0];
        av[1] = src[1];
    };
    auto convertA = [&](int s) {
        char* ab = dsm + (s & 1) * ABUF_B;
        uint2* dh = reinterpret_cast<uint2*>(ab + (arow * BKP + ak0) * 2);
        uint2* dl = reinterpret_cast<uint2*>(ab + AH_B + (arow * BKP + ak0) * 2);
        const float4* gg = reinterpret_cast<const float4*>(dsm + OFF_GM) + ((s * BKG + ak0) >> 2);
        const float4* bt = reinterpret_cast<const float4*>(dsm + OFF_BT) + ((s * BKG + ak0) >> 2);
        #pragma unroll
        for (int j = 0; j < 2; j++) {
            float4 x = av[j];
            float4 g = gg[j];
            float4 bb = bt[j];
            float o0 = (x.x - amean) * arstd * g.x + bb.x;
            float o1 = (x.y - amean) * arstd * g.y + bb.y;
            float o2 = (x.z - amean) * arstd * g.z + bb.z;
            float o3 = (x.w - amean) * arstd * g.w + bb.w;
            __nv_bfloat162 h01 = __floats2bfloat162_rn(o0, o1);
            __nv_bfloat162 h23 = __floats2bfloat162_rn(o2, o3);
            uint2 hp;
            hp.x = *reinterpret_cast<unsigned*>(&h01);
            hp.y = *reinterpret_cast<unsigned*>(&h23);
            dh[j] = hp;
            __nv_bfloat162 l01 = __floats2bfloat162_rn(o0 - __bfloat162float(h01.x),
                                                       o1 - __bfloat162float(h01.y));
            __nv_bfloat162 l23 = __floats2bfloat162_rn(o2 - __bfloat162float(h23.x),
                                                       o3 - __bfloat162float(h23.y));
            uint2 lp;
            lp.x = *reinterpret_cast<unsigned*>(&l01);
            lp.y = *reinterpret_cast<unsigned*>(&l23);
            dl[j] = lp;
        }
    };

    fetchA(0);
    issueB(0, 0);
    issueB(1, 1);
    convertA(0);
    fetchA(1);

    const int NIT = H / BKG;   // 32
    for (int i = 0; i < NIT; i++) {
        if (i < NIT - 1) asm volatile("cp.async.wait_group 1;\n" ::);
        else             asm volatile("cp.async.wait_group 0;\n" ::);
        __syncthreads();                      // A buf (i&1) + B stage i visible
        if (i + 2 < NIT) issueB(i + 2, (i + 2) % 3);

        const uint32_t abase = smem_u32 + (i & 1) * ABUF_B;
        const uint32_t bbase = smem_u32 + OFF_BRING + (i % 3) * BSTG_B;

        #pragma unroll
        for (int ks = 0; ks < BKG; ks += 16) {
            unsigned ah[4], al[4];
            {
                uint32_t aaddr = abase + (uint32_t)(a_lrow * BKP + ks + a_lcol) * 2;
                ldsm_x4(ah, aaddr);
                ldsm_x4(al, aaddr + AH_B);
            }
            #pragma unroll
            for (int p = 0; p < 6; p++) {
                unsigned bh[4], bl[4];
                uint32_t baddr = bbase +
                    (uint32_t)((b_lrow + p * 16) * BKP + ks + b_lcol) * 2;
                ldsm_x4(bh, baddr);
                ldsm_x4(bl, baddr + BH_B);
                mma_bf16(acc[2 * p],     ah, bh[0], bh[1]);
                mma_bf16(acc[2 * p + 1], ah, bh[2], bh[3]);
                mma_bf16(acc[2 * p],     ah, bl[0], bl[1]);
                mma_bf16(acc[2 * p + 1], ah, bl[2], bl[3]);
                mma_bf16(acc[2 * p],     al, bh[0], bh[1]);
                mma_bf16(acc[2 * p + 1], al, bh[2], bh[3]);
            }
            {   // tail nf = 12 (n 96..103 of this warp's half)
                unsigned bh[2], bl[2];
                uint32_t taddr = bbase +
                    (uint32_t)(t_lrow * BKP + ks + t_lcol) * 2;
                ldsm_x2(bh, taddr);
                ldsm_x2(bl, taddr + BH_B);
                mma_bf16(acc[12], ah, bh[0], bh[1]);
                mma_bf16(acc[12], ah, bl[0], bl[1]);
                mma_bf16(acc[12], al, bh[0], bh[1]);
            }
        }

        // prepare next A stage (writes buf (i+1)&1, not read until next sync)
        if (i + 1 < NIT) {
            convertA(i + 1);
            if (i + 2 < NIT) fetchA(i + 2);
        }
    }

    // ---- fused epilogue: all 128 rows staged at once ----
    __syncthreads();
    float* zs = (float*)dsm;                    // 128 x ZST floats = 107.5 KB
    #pragma unroll
    for (int nf = 0; nf < 13; nf++) {
        int r0  = wm * 16 + qr;
        int col = wn * 104 + nf * 8 + qp;
        *reinterpret_cast<float2*>(&zs[r0 * ZST + col]) =
            make_float2(acc[nf][0], acc[nf][1]);
        *reinterpret_cast<float2*>(&zs[(r0 + 8) * ZST + col]) =
            make_float2(acc[nf][2], acc[nf][3]);
    }
    __syncthreads();

    const float NEGF = -3.402823466e38f;
    const float POSF =  3.402823466e38f;
    #pragma unroll 1
    for (int rr = 0; rr < 8; rr++) {
        int rl = warp * 8 + rr;
        int gq_ = tm * BM + rl;
        size_t orow = ((size_t)b * QQ + gq_) * (NN + 1);

        float m = NEGF;
        if (lane < NN) {
            #pragma unroll
            for (int j = 0; j < KKK; j++)
                m = fmaxf(m, zs[rl * ZST + lane * KKK + j]);
            out_logits[orow + lane] = m;
        }

        float mv = (lane < NN) ? m : POSF;
        #pragma unroll
        for (int o = 16; o; o >>= 1)
            mv = fminf(mv, __shfl_xor_sync(0xffffffffu, mv, o));
        if (lane == 0) out_logits[orow + NN] = mv - 1.0f;

        float v  = (lane < NN) ? m : NEGF;
        int  idx = lane;
        #pragma unroll
        for (int o = 16; o; o >>= 1) {
            float ov = __shfl_xor_sync(0xffffffffu, v, o);
            int   oi = __shfl_xor_sync(0xffffffffu, idx, o);
            if (ov > v || (ov == v && oi < idx)) { v = ov; idx = oi; }
        }
        if (lane == 0 && write_pred)
            out_pred[(size_t)b * QQ + gq_] = (float)idx;
    }
}

// ---------------------------------------------------------------------------
extern "C" void kernel_launch(void* const* d_in, const int* in_sizes, int n_in,
                              void* d_out, int out_size) {
    const float* support = (const float*)d_in[0];
    const float* query   = (const float*)d_in[1];
    const float* gamma   = (const float*)d_in[2];
    const float* beta    = (const float*)d_in[3];
    float* out = (float*)d_out;

    cudaFuncSetAttribute(gemm_kernel,
                         cudaFuncAttributeMaxDynamicSharedMemorySize, SMEM_TOTAL);

    ln_kernel<<<SROWS / 8, 256>>>(support, gamma, beta);

    const int logits_elems = BATCH * QQ * (NN + 1);  // 1,376,256
    const int write_pred   = (out_size >= logits_elems + QROWS) ? 1 : 0;

    dim3 grid(1, QQ / BM, BATCH);   // (1, 16, 32) = 512 CTAs
    gemm_kernel<<<grid, NTHR, SMEM_TOTAL>>>(query, gamma, beta,
                                            out, out + logits_elems, write_pred);
}